// round 8
// baseline (speedup 1.0000x reference)
#include <cuda_runtime.h>
#include <cstdint>

#define B_ 8
#define T_ 2048
#define E_ 1024
#define C_ 128

// Scratch for projected Q, K, V (8 MB each).
// g_q, g_k: tf32-rounded, d-columns pair-permuted (phys = colperm(logical)).
// g_v: tf32-rounded, plain layout.
__device__ float g_k[B_ * T_ * C_];
__device__ float g_q[B_ * T_ * C_];
__device__ float g_v[B_ * T_ * C_];

// ---------------------------------------------------------------------------
// helpers
// ---------------------------------------------------------------------------
__device__ __forceinline__ float tfr(float x) {
    uint32_t h; asm("cvt.rna.tf32.f32 %0, %1;" : "=r"(h) : "f"(x));
    return __uint_as_float(h);
}
__device__ __forceinline__ float4 tfr4(float4 v) {
    return make_float4(tfr(v.x), tfr(v.y), tfr(v.z), tfr(v.w));
}
// pair permutation within each 8-col group: logical (t, t+4) -> physical (2t, 2t+1)
__device__ __forceinline__ int colperm(int c) {
    return (c & ~7) | (((c & 3) << 1) | ((c >> 2) & 1));
}
__device__ __forceinline__ void mma8(float* c, const uint32_t* a, uint32_t b0, uint32_t b1) {
    asm volatile("mma.sync.aligned.m16n8k8.row.col.f32.tf32.tf32.f32 "
        "{%0,%1,%2,%3}, {%4,%5,%6,%7}, {%8,%9}, {%0,%1,%2,%3};"
        : "+f"(c[0]), "+f"(c[1]), "+f"(c[2]), "+f"(c[3])
        : "r"(a[0]), "r"(a[1]), "r"(a[2]), "r"(a[3]), "r"(b0), "r"(b1));
}
#define U_(f) __float_as_uint(f)

// ---------------------------------------------------------------------------
// Kernel 1: QKV projection, tf32 mma.sync (mainloop unchanged from R6).
// Epilogue: tf32-round outputs; pair-permute d-columns for K and Q.
// ---------------------------------------------------------------------------
__global__ __launch_bounds__(256, 2) void qkv_mma(
    const float* __restrict__ x, const float* __restrict__ Wk,
    const float* __restrict__ Wq, const float* __restrict__ Wv)
{
    const int w = blockIdx.y;
    const float* __restrict__ W = (w == 0) ? Wk : ((w == 1) ? Wq : Wv);
    float* dst = (w == 0) ? g_k : ((w == 1) ? g_q : g_v);

    __shared__ float Xs[128 * 36];
    __shared__ float Ws[32 * 132];

    const int tid = threadIdx.x;
    const int wid = tid >> 5, lane = tid & 31, gid = lane >> 2, tig = lane & 3;
    const int wm = wid >> 1, wn = wid & 1;
    const int m0 = blockIdx.x * 128;

    float acc[2][8][4];
#pragma unroll
    for (int mt = 0; mt < 2; mt++)
#pragma unroll
        for (int nt = 0; nt < 8; nt++)
#pragma unroll
            for (int i = 0; i < 4; i++) acc[mt][nt][i] = 0.f;

    float4 px[4], pw[4];

#pragma unroll
    for (int e = 0; e < 4; e++) {
        int idx = tid + e * 256;
        px[e] = *(const float4*)(x + (size_t)(m0 + (idx >> 3)) * E_ + (idx & 7) * 4);
        pw[e] = *(const float4*)(W + (size_t)(idx >> 5) * C_ + (idx & 31) * 4);
    }
#pragma unroll
    for (int e = 0; e < 4; e++) {
        int idx = tid + e * 256;
        *(float4*)(&Xs[(idx >> 3) * 36 + (idx & 7) * 4])   = tfr4(px[e]);
        *(float4*)(&Ws[(idx >> 5) * 132 + (idx & 31) * 4]) = tfr4(pw[e]);
    }
    __syncthreads();

    for (int it = 0; it < 32; it++) {
        if (it < 31) {
            const int k0 = (it + 1) * 32;
#pragma unroll
            for (int e = 0; e < 4; e++) {
                int idx = tid + e * 256;
                px[e] = *(const float4*)(x + (size_t)(m0 + (idx >> 3)) * E_ + k0 + (idx & 7) * 4);
                pw[e] = *(const float4*)(W + (size_t)(k0 + (idx >> 5)) * C_ + (idx & 31) * 4);
            }
        }

#pragma unroll
        for (int ks = 0; ks < 4; ks++) {
            const int c0 = ks * 8 + tig;
            uint32_t a[2][4];
#pragma unroll
            for (int mt = 0; mt < 2; mt++) {
                int r0 = wm * 32 + mt * 16 + gid;
                a[mt][0] = U_(Xs[r0 * 36 + c0]);
                a[mt][1] = U_(Xs[(r0 + 8) * 36 + c0]);
                a[mt][2] = U_(Xs[r0 * 36 + c0 + 4]);
                a[mt][3] = U_(Xs[(r0 + 8) * 36 + c0 + 4]);
            }
#pragma unroll
            for (int nt = 0; nt < 8; nt++) {
                int n = wn * 64 + nt * 8 + gid;
                uint32_t b0 = U_(Ws[(ks * 8 + tig) * 132 + n]);
                uint32_t b1 = U_(Ws[(ks * 8 + tig + 4) * 132 + n]);
#pragma unroll
                for (int mt = 0; mt < 2; mt++)
                    mma8(acc[mt][nt], a[mt], b0, b1);
            }
        }
        __syncthreads();

        if (it < 31) {
#pragma unroll
            for (int e = 0; e < 4; e++) {
                int idx = tid + e * 256;
                *(float4*)(&Xs[(idx >> 3) * 36 + (idx & 7) * 4])   = tfr4(px[e]);
                *(float4*)(&Ws[(idx >> 5) * 132 + (idx & 31) * 4]) = tfr4(pw[e]);
            }
            __syncthreads();
        }
    }

    // epilogue: tf32-round; permute d-cols for K(w=0) and Q(w=1), plain for V
#pragma unroll
    for (int mt = 0; mt < 2; mt++) {
        int r0 = m0 + wm * 32 + mt * 16 + gid;
#pragma unroll
        for (int nt = 0; nt < 8; nt++) {
            int c = wn * 64 + nt * 8 + tig * 2;
            float v00 = tfr(acc[mt][nt][0]), v01 = tfr(acc[mt][nt][1]);
            float v10 = tfr(acc[mt][nt][2]), v11 = tfr(acc[mt][nt][3]);
            if (w == 2) {
                *(float2*)(dst + (size_t)r0 * C_ + c)       = make_float2(v00, v01);
                *(float2*)(dst + (size_t)(r0 + 8) * C_ + c) = make_float2(v10, v11);
            } else {
                int p0 = colperm(c), p1 = colperm(c + 1);
                dst[(size_t)r0 * C_ + p0]       = v00;
                dst[(size_t)r0 * C_ + p1]       = v01;
                dst[(size_t)(r0 + 8) * C_ + p0] = v10;
                dst[(size_t)(r0 + 8) * C_ + p1] = v11;
            }
        }
    }
}

// ---------------------------------------------------------------------------
// Kernel 2: causal flash attention, tf32 mma.sync, 2 CTA/SM.
// Operands arrive pre-rounded; Q/K pair-permuted -> LDS.64 fragment loads.
// Ps stored key-pair-permuted by the score writer.
// ---------------------------------------------------------------------------
#define QSD 132
#define PSD 68
#define ATTN_SMEM_BYTES ((64 * QSD + 64 * QSD + 64 * PSD + 192) * 4)

__global__ __launch_bounds__(256, 2) void attn_mma(float* __restrict__ out)
{
    extern __shared__ float sm[];
    float* Qs   = sm;                    // [64][132] (pair-permuted d)
    float* KV   = sm + 64 * QSD;         // [64][132] K (permuted) then V (plain)
    float* Ps   = KV + 64 * QSD;         // [64][68]  (pair-permuted keys)
    float* mrow = Ps + 64 * PSD;
    float* lrow = mrow + 64;
    float* srow = lrow + 64;

    const int tid = threadIdx.x;
    const int wid = tid >> 5, lane = tid & 31, gid = lane >> 2, tig = lane & 3;
    const int wm = wid >> 1, wn = wid & 1;

    // balanced mapping: co-resident pair (bid, bid+148) has qt sum == 31
    const int bb = blockIdx.x;
    int b, qt;
    if (bb < 128) { b = bb >> 5;               qt = 31 - (bb & 31); }
    else          { b = 4 + ((bb - 128) >> 5); qt = ((bb & 31) + 12) & 31; }

    // ---- prologue: copy Q tile + prefetch K[0] (pure copies, pre-rounded) ----
    const float4* qg = (const float4*)(g_q + (size_t)(b * T_ + qt * 64) * C_);
    float4 kreg[8];
    {
        const float4* kg = (const float4*)(g_k + (size_t)(b * T_) * C_);
#pragma unroll
        for (int e = 0; e < 8; e++) kreg[e] = kg[tid + e * 256];
    }
#pragma unroll
    for (int e = 0; e < 8; e++) {
        int idx = tid + e * 256;
        *(float4*)(&Qs[(idx >> 5) * QSD + (idx & 31) * 4]) = qg[idx];
    }
    if (tid < 64) { mrow[tid] = -1e30f; lrow[tid] = 0.f; }
    __syncthreads();
#pragma unroll
    for (int e = 0; e < 8; e++) {
        int idx = tid + e * 256;
        *(float4*)(&KV[(idx >> 5) * QSD + (idx & 31) * 4]) = kreg[e];
    }
    __syncthreads();   // K visible

    float o[8][4];
#pragma unroll
    for (int nt = 0; nt < 8; nt++)
#pragma unroll
        for (int i = 0; i < 4; i++) o[nt][i] = 0.f;

    const float scale = 0.08838834764831845f;   // 1/sqrt(128)
    const int r0 = wm * 16 + gid;

    for (int kt = 0; kt <= qt; kt++) {
        // ---- issue V[kt] LDG (consumed after sync c) ----
        float4 vreg[8];
        {
            const float4* vg = (const float4*)(g_v + (size_t)(b * T_ + kt * 64) * C_);
#pragma unroll
            for (int e = 0; e < 8; e++) vreg[e] = vg[tid + e * 256];
        }

        // ---- phase A: S = Q @ K^T (LDS.64 fragment loads) ----
        float s[4][4];
#pragma unroll
        for (int nt = 0; nt < 4; nt++)
#pragma unroll
            for (int i = 0; i < 4; i++) s[nt][i] = 0.f;

#pragma unroll 4
        for (int ks = 0; ks < 16; ks++) {
            const int cp = ks * 8 + tig * 2;     // physical pair base
            uint32_t a[4];
            float2 a02 = *(const float2*)(&Qs[r0 * QSD + cp]);
            float2 a13 = *(const float2*)(&Qs[(r0 + 8) * QSD + cp]);
            a[0] = U_(a02.x); a[2] = U_(a02.y);
            a[1] = U_(a13.x); a[3] = U_(a13.y);
#pragma unroll
            for (int nt = 0; nt < 4; nt++) {
                int n = wn * 32 + nt * 8 + gid;
                float2 bp = *(const float2*)(&KV[n * QSD + cp]);
                mma8(s[nt], a, U_(bp.x), U_(bp.y));
            }
        }

        // scale + causal mask + store S -> Ps (key-pair-permuted positions)
        const bool diag = (kt == qt);
#pragma unroll
        for (int nt = 0; nt < 4; nt++) {
            int kb = wn * 32 + nt * 8 + tig * 2;
            float v0 = s[nt][0] * scale, v1 = s[nt][1] * scale;
            float v2 = s[nt][2] * scale, v3 = s[nt][3] * scale;
            if (diag) {
                if (kb     > r0)     v0 = -1e30f;
                if (kb + 1 > r0)     v1 = -1e30f;
                if (kb     > r0 + 8) v2 = -1e30f;
                if (kb + 1 > r0 + 8) v3 = -1e30f;
            }
            int p0 = colperm(kb), p1 = colperm(kb + 1);
            Ps[r0 * PSD + p0]       = v0;
            Ps[r0 * PSD + p1]       = v1;
            Ps[(r0 + 8) * PSD + p0] = v2;
            Ps[(r0 + 8) * PSD + p1] = v3;
        }
        __syncthreads();   // (c) Ps complete; K reads done

        // ---- STS V (plain copy; overwrites K in union) ----
#pragma unroll
        for (int e = 0; e < 8; e++) {
            int idx = tid + e * 256;
            *(float4*)(&KV[(idx >> 5) * QSD + (idx & 31) * 4]) = vreg[e];
        }

        // ---- issue K[kt+1] LDG (consumed after phase B) ----
        if (kt < qt) {
            const float4* kg = (const float4*)(g_k + (size_t)(b * T_ + (kt + 1) * 64) * C_);
#pragma unroll
            for (int e = 0; e < 8; e++) kreg[e] = kg[tid + e * 256];
        }

        // ---- online softmax: 4 threads per row (permutation-agnostic) ----
        {
            int r = tid >> 2, seg = tid & 3;
            float* pr = Ps + r * PSD + seg * 16;
            float4 p0 = *(float4*)(pr), p1 = *(float4*)(pr + 4);
            float4 p2 = *(float4*)(pr + 8), p3 = *(float4*)(pr + 12);
            float mx = fmaxf(fmaxf(fmaxf(p0.x, p0.y), fmaxf(p0.z, p0.w)),
                     fmaxf(fmaxf(fmaxf(p1.x, p1.y), fmaxf(p1.z, p1.w)),
                     fmaxf(fmaxf(fmaxf(p2.x, p2.y), fmaxf(p2.z, p2.w)),
                           fmaxf(fmaxf(p3.x, p3.y), fmaxf(p3.z, p3.w)))));
            mx = fmaxf(mx, __shfl_xor_sync(0xffffffffu, mx, 1));
            mx = fmaxf(mx, __shfl_xor_sync(0xffffffffu, mx, 2));
            float mold = mrow[r];
            float newm = fmaxf(mold, mx);
            float fac  = __expf(mold - newm);
            p0.x = __expf(p0.x - newm); p0.y = __expf(p0.y - newm);
            p0.z = __expf(p0.z - newm); p0.w = __expf(p0.w - newm);
            p1.x = __expf(p1.x - newm); p1.y = __expf(p1.y - newm);
            p1.z = __expf(p1.z - newm); p1.w = __expf(p1.w - newm);
            p2.x = __expf(p2.x - newm); p2.y = __expf(p2.y - newm);
            p2.z = __expf(p2.z - newm); p2.w = __expf(p2.w - newm);
            p3.x = __expf(p3.x - newm); p3.y = __expf(p3.y - newm);
            p3.z = __expf(p3.z - newm); p3.w = __expf(p3.w - newm);
            float sum = (p0.x + p0.y + p0.z + p0.w) + (p1.x + p1.y + p1.z + p1.w)
                      + (p2.x + p2.y + p2.z + p2.w) + (p3.x + p3.y + p3.z + p3.w);
            *(float4*)(pr)      = p0;
            *(float4*)(pr + 4)  = p1;
            *(float4*)(pr + 8)  = p2;
            *(float4*)(pr + 12) = p3;
            sum += __shfl_xor_sync(0xffffffffu, sum, 1);
            sum += __shfl_xor_sync(0xffffffffu, sum, 2);
            if (seg == 0) {
                lrow[r] = lrow[r] * fac + sum;
                mrow[r] = newm;
                srow[r] = fac;
            }
        }
        __syncthreads();   // (d) V visible, probs + stats ready

        // ---- rescale accumulators ----
        {
            float f0 = srow[r0], f1 = srow[r0 + 8];
#pragma unroll
            for (int nt = 0; nt < 8; nt++) {
                o[nt][0] *= f0; o[nt][1] *= f0;
                o[nt][2] *= f1; o[nt][3] *= f1;
            }
        }

        // ---- phase B: O += P @ V (P via LDS.64 from permuted Ps) ----
#pragma unroll 2
        for (int ks = 0; ks < 8; ks++) {
            const int cp = ks * 8 + tig * 2;
            uint32_t a[4];
            float2 a02 = *(const float2*)(&Ps[r0 * PSD + cp]);
            float2 a13 = *(const float2*)(&Ps[(r0 + 8) * PSD + cp]);
            a[0] = U_(tfr(a02.x)); a[2] = U_(tfr(a02.y));
            a[1] = U_(tfr(a13.x)); a[3] = U_(tfr(a13.y));
#pragma unroll
            for (int nt = 0; nt < 8; nt++) {
                int n = wn * 64 + nt * 8 + gid;
                uint32_t b0 = U_(KV[(ks * 8 + tig) * QSD + n]);
                uint32_t b1 = U_(KV[(ks * 8 + tig + 4) * QSD + n]);
                mma8(o[nt], a, b0, b1);
            }
        }
        __syncthreads();   // (a) phase B done; KV free

        // ---- STS K[kt+1] (pure copy) ----
        if (kt < qt) {
#pragma unroll
            for (int e = 0; e < 8; e++) {
                int idx = tid + e * 256;
                *(float4*)(&KV[(idx >> 5) * QSD + (idx & 31) * 4]) = kreg[e];
            }
        }
        __syncthreads();   // (b) K visible
    }

    // ---- epilogue: normalize and store (standard layout) ----
    {
        float inv0 = 1.f / lrow[r0], inv1 = 1.f / lrow[r0 + 8];
        size_t base = (size_t)(b * T_ + qt * 64);
#pragma unroll
        for (int nt = 0; nt < 8; nt++) {
            int c = wn * 64 + nt * 8 + tig * 2;
            *(float2*)(out + (base + r0) * C_ + c)     = make_float2(o[nt][0] * inv0, o[nt][1] * inv0);
            *(float2*)(out + (base + r0 + 8) * C_ + c) = make_float2(o[nt][2] * inv1, o[nt][3] * inv1);
        }
    }
}

// ---------------------------------------------------------------------------
extern "C" void kernel_launch(void* const* d_in, const int* in_sizes, int n_in,
                              void* d_out, int out_size)
{
    const float* x  = (const float*)d_in[0];
    const float* Wk = (const float*)d_in[1];
    const float* Wq = (const float*)d_in[2];
    const float* Wv = (const float*)d_in[3];
    float* out = (float*)d_out;

    cudaFuncSetAttribute(attn_mma,
                         cudaFuncAttributeMaxDynamicSharedMemorySize,
                         ATTN_SMEM_BYTES);

    dim3 qkv_grid(128, 3);
    qkv_mma<<<qkv_grid, 256>>>(x, Wk, Wq, Wv);

    attn_mma<<<B_ * (T_ / 64), 256, ATTN_SMEM_BYTES>>>(out);
}

// round 9
// speedup vs baseline: 1.0355x; 1.0355x over previous
#include <cuda_runtime.h>
#include <cstdint>

#define B_ 8
#define T_ 2048
#define E_ 1024
#define C_ 128

// Scratch for projected Q, K, V (8 MB each), stored tf32-rounded.
__device__ float g_k[B_ * T_ * C_];
__device__ float g_q[B_ * T_ * C_];
__device__ float g_v[B_ * T_ * C_];

// ---------------------------------------------------------------------------
// helpers
// ---------------------------------------------------------------------------
__device__ __forceinline__ float tfr(float x) {
    uint32_t h; asm("cvt.rna.tf32.f32 %0, %1;" : "=r"(h) : "f"(x));
    return __uint_as_float(h);
}
__device__ __forceinline__ float4 tfr4(float4 v) {
    return make_float4(tfr(v.x), tfr(v.y), tfr(v.z), tfr(v.w));
}
__device__ __forceinline__ void mma8(float* c, const uint32_t* a, uint32_t b0, uint32_t b1) {
    asm volatile("mma.sync.aligned.m16n8k8.row.col.f32.tf32.tf32.f32 "
        "{%0,%1,%2,%3}, {%4,%5,%6,%7}, {%8,%9}, {%0,%1,%2,%3};"
        : "+f"(c[0]), "+f"(c[1]), "+f"(c[2]), "+f"(c[3])
        : "r"(a[0]), "r"(a[1]), "r"(a[2]), "r"(a[3]), "r"(b0), "r"(b1));
}
#define U_(f) __float_as_uint(f)

// ---------------------------------------------------------------------------
// Kernel 1: QKV projection, tf32 mma.sync, M-tile 64 (wave-balance fix).
// Y[16384,128] = X[16384,1024] @ W[1024,128].  grid=(256,3), 256 thr, 3 CTA/SM.
// Block tile 64x128, BK=32. 8 warps 4(m)x2(n), warp tile 16x64.
// Epilogue stores tf32-rounded outputs (consumed as tf32 by attention).
// ---------------------------------------------------------------------------
__global__ __launch_bounds__(256, 3) void qkv_mma(
    const float* __restrict__ x, const float* __restrict__ Wk,
    const float* __restrict__ Wq, const float* __restrict__ Wv)
{
    const int w = blockIdx.y;
    const float* __restrict__ W = (w == 0) ? Wk : ((w == 1) ? Wq : Wv);
    float* dst = (w == 0) ? g_k : ((w == 1) ? g_q : g_v);

    __shared__ float Xs[64 * 36];     // 64 rows x 32 cols, pad->36
    __shared__ float Ws[32 * 132];    // 32 k x 128 n, pad->132

    const int tid = threadIdx.x;
    const int wid = tid >> 5, lane = tid & 31, gid = lane >> 2, tig = lane & 3;
    const int wm = wid >> 1, wn = wid & 1;
    const int m0 = blockIdx.x * 64;

    float acc[8][4];
#pragma unroll
    for (int nt = 0; nt < 8; nt++)
#pragma unroll
        for (int i = 0; i < 4; i++) acc[nt][i] = 0.f;

    float4 px[2], pw[4];

    // ---- load tile 0 ----
#pragma unroll
    for (int e = 0; e < 2; e++) {
        int idx = tid + e * 256;      // X: 512 float4, row=idx>>3, c4=idx&7
        px[e] = *(const float4*)(x + (size_t)(m0 + (idx >> 3)) * E_ + (idx & 7) * 4);
    }
#pragma unroll
    for (int e = 0; e < 4; e++) {
        int idx = tid + e * 256;      // W: 1024 float4, row=idx>>5, c4=idx&31
        pw[e] = *(const float4*)(W + (size_t)(idx >> 5) * C_ + (idx & 31) * 4);
    }
#pragma unroll
    for (int e = 0; e < 2; e++) {
        int idx = tid + e * 256;
        *(float4*)(&Xs[(idx >> 3) * 36 + (idx & 7) * 4]) = tfr4(px[e]);
    }
#pragma unroll
    for (int e = 0; e < 4; e++) {
        int idx = tid + e * 256;
        *(float4*)(&Ws[(idx >> 5) * 132 + (idx & 31) * 4]) = tfr4(pw[e]);
    }
    __syncthreads();

    for (int it = 0; it < 32; it++) {
        if (it < 31) {
            const int k0 = (it + 1) * 32;
#pragma unroll
            for (int e = 0; e < 2; e++) {
                int idx = tid + e * 256;
                px[e] = *(const float4*)(x + (size_t)(m0 + (idx >> 3)) * E_ + k0 + (idx & 7) * 4);
            }
#pragma unroll
            for (int e = 0; e < 4; e++) {
                int idx = tid + e * 256;
                pw[e] = *(const float4*)(W + (size_t)(k0 + (idx >> 5)) * C_ + (idx & 31) * 4);
            }
        }

#pragma unroll
        for (int ks = 0; ks < 4; ks++) {
            const int c0 = ks * 8 + tig;
            const int r0 = wm * 16 + gid;
            uint32_t a[4];
            a[0] = U_(Xs[r0 * 36 + c0]);
            a[1] = U_(Xs[(r0 + 8) * 36 + c0]);
            a[2] = U_(Xs[r0 * 36 + c0 + 4]);
            a[3] = U_(Xs[(r0 + 8) * 36 + c0 + 4]);
#pragma unroll
            for (int nt = 0; nt < 8; nt++) {
                int n = wn * 64 + nt * 8 + gid;
                uint32_t b0 = U_(Ws[(ks * 8 + tig) * 132 + n]);
                uint32_t b1 = U_(Ws[(ks * 8 + tig + 4) * 132 + n]);
                mma8(acc[nt], a, b0, b1);
            }
        }
        __syncthreads();

        if (it < 31) {
#pragma unroll
            for (int e = 0; e < 2; e++) {
                int idx = tid + e * 256;
                *(float4*)(&Xs[(idx >> 3) * 36 + (idx & 7) * 4]) = tfr4(px[e]);
            }
#pragma unroll
            for (int e = 0; e < 4; e++) {
                int idx = tid + e * 256;
                *(float4*)(&Ws[(idx >> 5) * 132 + (idx & 31) * 4]) = tfr4(pw[e]);
            }
            __syncthreads();
        }
    }

    // ---- epilogue: tf32-round and store ----
    {
        int r0 = m0 + wm * 16 + gid;
#pragma unroll
        for (int nt = 0; nt < 8; nt++) {
            int c = wn * 64 + nt * 8 + tig * 2;
            *(float2*)(dst + (size_t)r0 * C_ + c)       = make_float2(tfr(acc[nt][0]), tfr(acc[nt][1]));
            *(float2*)(dst + (size_t)(r0 + 8) * C_ + c) = make_float2(tfr(acc[nt][2]), tfr(acc[nt][3]));
        }
    }
}

// ---------------------------------------------------------------------------
// Kernel 2: causal flash attention, tf32 mma.sync, 2 CTA/SM (R7 structure).
// Operands pre-rounded by producer -> all STS are pure copies.
// Softmax stores tf32-rounded probs -> phase B has no CVTs.
// ---------------------------------------------------------------------------
#define QSD 132
#define PSD 68
#define ATTN_SMEM_BYTES ((64 * QSD + 64 * QSD + 64 * PSD + 192) * 4)

__global__ __launch_bounds__(256, 2) void attn_mma(float* __restrict__ out)
{
    extern __shared__ float sm[];
    float* Qs   = sm;                    // [64][132]
    float* KV   = sm + 64 * QSD;         // [64][132] K then V (union)
    float* Ps   = KV + 64 * QSD;         // [64][68]
    float* mrow = Ps + 64 * PSD;
    float* lrow = mrow + 64;
    float* srow = lrow + 64;

    const int tid = threadIdx.x;
    const int wid = tid >> 5, lane = tid & 31, gid = lane >> 2, tig = lane & 3;
    const int wm = wid >> 1, wn = wid & 1;

    // balanced mapping: co-resident pair (bid, bid+148) has qt sum == 31
    const int bb = blockIdx.x;
    int b, qt;
    if (bb < 128) { b = bb >> 5;               qt = 31 - (bb & 31); }
    else          { b = 4 + ((bb - 128) >> 5); qt = ((bb & 31) + 12) & 31; }

    // ---- prologue: copy Q tile + prefetch K[0] (pure copies) ----
    const float4* qg = (const float4*)(g_q + (size_t)(b * T_ + qt * 64) * C_);
    float4 kreg[8];
    {
        const float4* kg = (const float4*)(g_k + (size_t)(b * T_) * C_);
#pragma unroll
        for (int e = 0; e < 8; e++) kreg[e] = kg[tid + e * 256];
    }
#pragma unroll
    for (int e = 0; e < 8; e++) {
        int idx = tid + e * 256;
        *(float4*)(&Qs[(idx >> 5) * QSD + (idx & 31) * 4]) = qg[idx];
    }
    if (tid < 64) { mrow[tid] = -1e30f; lrow[tid] = 0.f; }
    __syncthreads();
#pragma unroll
    for (int e = 0; e < 8; e++) {
        int idx = tid + e * 256;
        *(float4*)(&KV[(idx >> 5) * QSD + (idx & 31) * 4]) = kreg[e];
    }
    __syncthreads();   // K visible

    float o[8][4];
#pragma unroll
    for (int nt = 0; nt < 8; nt++)
#pragma unroll
        for (int i = 0; i < 4; i++) o[nt][i] = 0.f;

    const float scale = 0.08838834764831845f;   // 1/sqrt(128)
    const int r0 = wm * 16 + gid;

    for (int kt = 0; kt <= qt; kt++) {
        // ---- issue V[kt] LDG (consumed after sync c) ----
        float4 vreg[8];
        {
            const float4* vg = (const float4*)(g_v + (size_t)(b * T_ + kt * 64) * C_);
#pragma unroll
            for (int e = 0; e < 8; e++) vreg[e] = vg[tid + e * 256];
        }

        // ---- phase A: S = Q @ K^T ----
        float s[4][4];
#pragma unroll
        for (int nt = 0; nt < 4; nt++)
#pragma unroll
            for (int i = 0; i < 4; i++) s[nt][i] = 0.f;

#pragma unroll 4
        for (int ks = 0; ks < 16; ks++) {
            const int c0 = ks * 8 + tig;
            uint32_t a[4];
            a[0] = U_(Qs[r0 * QSD + c0]);
            a[1] = U_(Qs[(r0 + 8) * QSD + c0]);
            a[2] = U_(Qs[r0 * QSD + c0 + 4]);
            a[3] = U_(Qs[(r0 + 8) * QSD + c0 + 4]);
#pragma unroll
            for (int nt = 0; nt < 4; nt++) {
                int n = wn * 32 + nt * 8 + gid;
                uint32_t b0 = U_(KV[n * QSD + c0]);
                uint32_t b1 = U_(KV[n * QSD + c0 + 4]);
                mma8(s[nt], a, b0, b1);
            }
        }

        // scale + causal mask + store S -> Ps
        const bool diag = (kt == qt);
#pragma unroll
        for (int nt = 0; nt < 4; nt++) {
            int kb = wn * 32 + nt * 8 + tig * 2;
            float v0 = s[nt][0] * scale, v1 = s[nt][1] * scale;
            float v2 = s[nt][2] * scale, v3 = s[nt][3] * scale;
            if (diag) {
                if (kb     > r0)     v0 = -1e30f;
                if (kb + 1 > r0)     v1 = -1e30f;
                if (kb     > r0 + 8) v2 = -1e30f;
                if (kb + 1 > r0 + 8) v3 = -1e30f;
            }
            Ps[r0 * PSD + kb]           = v0;
            Ps[r0 * PSD + kb + 1]       = v1;
            Ps[(r0 + 8) * PSD + kb]     = v2;
            Ps[(r0 + 8) * PSD + kb + 1] = v3;
        }
        __syncthreads();   // (c) Ps complete; K reads done

        // ---- STS V (pure copy; overwrites K in union) ----
#pragma unroll
        for (int e = 0; e < 8; e++) {
            int idx = tid + e * 256;
            *(float4*)(&KV[(idx >> 5) * QSD + (idx & 31) * 4]) = vreg[e];
        }

        // ---- issue K[kt+1] LDG (consumed after phase B) ----
        if (kt < qt) {
            const float4* kg = (const float4*)(g_k + (size_t)(b * T_ + (kt + 1) * 64) * C_);
#pragma unroll
            for (int e = 0; e < 8; e++) kreg[e] = kg[tid + e * 256];
        }

        // ---- online softmax: 4 threads per row; store tf32-rounded probs ----
        {
            int r = tid >> 2, seg = tid & 3;
            float* pr = Ps + r * PSD + seg * 16;
            float4 p0 = *(float4*)(pr), p1 = *(float4*)(pr + 4);
            float4 p2 = *(float4*)(pr + 8), p3 = *(float4*)(pr + 12);
            float mx = fmaxf(fmaxf(fmaxf(p0.x, p0.y), fmaxf(p0.z, p0.w)),
                     fmaxf(fmaxf(fmaxf(p1.x, p1.y), fmaxf(p1.z, p1.w)),
                     fmaxf(fmaxf(fmaxf(p2.x, p2.y), fmaxf(p2.z, p2.w)),
                           fmaxf(fmaxf(p3.x, p3.y), fmaxf(p3.z, p3.w)))));
            mx = fmaxf(mx, __shfl_xor_sync(0xffffffffu, mx, 1));
            mx = fmaxf(mx, __shfl_xor_sync(0xffffffffu, mx, 2));
            float mold = mrow[r];
            float newm = fmaxf(mold, mx);
            float fac  = __expf(mold - newm);
            p0.x = __expf(p0.x - newm); p0.y = __expf(p0.y - newm);
            p0.z = __expf(p0.z - newm); p0.w = __expf(p0.w - newm);
            p1.x = __expf(p1.x - newm); p1.y = __expf(p1.y - newm);
            p1.z = __expf(p1.z - newm); p1.w = __expf(p1.w - newm);
            p2.x = __expf(p2.x - newm); p2.y = __expf(p2.y - newm);
            p2.z = __expf(p2.z - newm); p2.w = __expf(p2.w - newm);
            p3.x = __expf(p3.x - newm); p3.y = __expf(p3.y - newm);
            p3.z = __expf(p3.z - newm); p3.w = __expf(p3.w - newm);
            float sum = (p0.x + p0.y + p0.z + p0.w) + (p1.x + p1.y + p1.z + p1.w)
                      + (p2.x + p2.y + p2.z + p2.w) + (p3.x + p3.y + p3.z + p3.w);
            *(float4*)(pr)      = tfr4(p0);
            *(float4*)(pr + 4)  = tfr4(p1);
            *(float4*)(pr + 8)  = tfr4(p2);
            *(float4*)(pr + 12) = tfr4(p3);
            sum += __shfl_xor_sync(0xffffffffu, sum, 1);
            sum += __shfl_xor_sync(0xffffffffu, sum, 2);
            if (seg == 0) {
                lrow[r] = lrow[r] * fac + sum;
                mrow[r] = newm;
                srow[r] = fac;
            }
        }
        __syncthreads();   // (d) V visible, probs + stats ready

        // ---- rescale accumulators ----
        {
            float f0 = srow[r0], f1 = srow[r0 + 8];
#pragma unroll
            for (int nt = 0; nt < 8; nt++) {
                o[nt][0] *= f0; o[nt][1] *= f0;
                o[nt][2] *= f1; o[nt][3] *= f1;
            }
        }

        // ---- phase B: O += P @ V (probs already tf32) ----
#pragma unroll 2
        for (int ks = 0; ks < 8; ks++) {
            const int c0 = ks * 8 + tig;
            uint32_t a[4];
            a[0] = U_(Ps[r0 * PSD + c0]);
            a[1] = U_(Ps[(r0 + 8) * PSD + c0]);
            a[2] = U_(Ps[r0 * PSD + c0 + 4]);
            a[3] = U_(Ps[(r0 + 8) * PSD + c0 + 4]);
#pragma unroll
            for (int nt = 0; nt < 8; nt++) {
                int n = wn * 64 + nt * 8 + gid;
                uint32_t b0 = U_(KV[(ks * 8 + tig) * QSD + n]);
                uint32_t b1 = U_(KV[(ks * 8 + tig + 4) * QSD + n]);
                mma8(o[nt], a, b0, b1);
            }
        }
        __syncthreads();   // (a) phase B done; KV free

        // ---- STS K[kt+1] (pure copy) ----
        if (kt < qt) {
#pragma unroll
            for (int e = 0; e < 8; e++) {
                int idx = tid + e * 256;
                *(float4*)(&KV[(idx >> 5) * QSD + (idx & 31) * 4]) = kreg[e];
            }
        }
        __syncthreads();   // (b) K visible
    }

    // ---- epilogue: normalize and store ----
    {
        float inv0 = 1.f / lrow[r0], inv1 = 1.f / lrow[r0 + 8];
        size_t base = (size_t)(b * T_ + qt * 64);
#pragma unroll
        for (int nt = 0; nt < 8; nt++) {
            int c = wn * 64 + nt * 8 + tig * 2;
            *(float2*)(out + (base + r0) * C_ + c)     = make_float2(o[nt][0] * inv0, o[nt][1] * inv0);
            *(float2*)(out + (base + r0 + 8) * C_ + c) = make_float2(o[nt][2] * inv1, o[nt][3] * inv1);
        }
    }
}

// ---------------------------------------------------------------------------
extern "C" void kernel_launch(void* const* d_in, const int* in_sizes, int n_in,
                              void* d_out, int out_size)
{
    const float* x  = (const float*)d_in[0];
    const float* Wk = (const float*)d_in[1];
    const float* Wq = (const float*)d_in[2];
    const float* Wv = (const float*)d_in[3];
    float* out = (float*)d_out;

    cudaFuncSetAttribute(attn_mma,
                         cudaFuncAttributeMaxDynamicSharedMemorySize,
                         ATTN_SMEM_BYTES);

    dim3 qkv_grid(256, 3);
    qkv_mma<<<qkv_grid, 256>>>(x, Wk, Wq, Wv);

    attn_mma<<<B_ * (T_ / 64), 256, ATTN_SMEM_BYTES>>>(out);
}

// round 10
// speedup vs baseline: 1.2459x; 1.2033x over previous
#include <cuda_runtime.h>
#include <cstdint>

#define B_ 8
#define T_ 2048
#define E_ 1024
#define C_ 128

// Scratch for projected Q, K, V (8 MB each), stored tf32-rounded.
__device__ float g_k[B_ * T_ * C_];
__device__ float g_q[B_ * T_ * C_];
__device__ float g_v[B_ * T_ * C_];

// ---------------------------------------------------------------------------
// helpers
// ---------------------------------------------------------------------------
__device__ __forceinline__ float tfr(float x) {
    uint32_t h; asm("cvt.rna.tf32.f32 %0, %1;" : "=r"(h) : "f"(x));
    return __uint_as_float(h);
}
__device__ __forceinline__ float4 tfr4(float4 v) {
    return make_float4(tfr(v.x), tfr(v.y), tfr(v.z), tfr(v.w));
}
__device__ __forceinline__ void mma8(float* c, const uint32_t* a, uint32_t b0, uint32_t b1) {
    asm volatile("mma.sync.aligned.m16n8k8.row.col.f32.tf32.tf32.f32 "
        "{%0,%1,%2,%3}, {%4,%5,%6,%7}, {%8,%9}, {%0,%1,%2,%3};"
        : "+f"(c[0]), "+f"(c[1]), "+f"(c[2]), "+f"(c[3])
        : "r"(a[0]), "r"(a[1]), "r"(a[2]), "r"(a[3]), "r"(b0), "r"(b1));
}
#define U_(f) __float_as_uint(f)

// ---------------------------------------------------------------------------
// Kernel 1: QKV projection, tf32 mma.sync (R7 structure: M128, BK32, 2 CTA/SM).
// Epilogue stores tf32-rounded outputs (attention consumes them raw).
// ---------------------------------------------------------------------------
__global__ __launch_bounds__(256, 2) void qkv_mma(
    const float* __restrict__ x, const float* __restrict__ Wk,
    const float* __restrict__ Wq, const float* __restrict__ Wv)
{
    const int w = blockIdx.y;
    const float* __restrict__ W = (w == 0) ? Wk : ((w == 1) ? Wq : Wv);
    float* dst = (w == 0) ? g_k : ((w == 1) ? g_q : g_v);

    __shared__ float Xs[128 * 36];
    __shared__ float Ws[32 * 132];

    const int tid = threadIdx.x;
    const int wid = tid >> 5, lane = tid & 31, gid = lane >> 2, tig = lane & 3;
    const int wm = wid >> 1, wn = wid & 1;
    const int m0 = blockIdx.x * 128;

    float acc[2][8][4];
#pragma unroll
    for (int mt = 0; mt < 2; mt++)
#pragma unroll
        for (int nt = 0; nt < 8; nt++)
#pragma unroll
            for (int i = 0; i < 4; i++) acc[mt][nt][i] = 0.f;

    float4 px[4], pw[4];

#pragma unroll
    for (int e = 0; e < 4; e++) {
        int idx = tid + e * 256;
        px[e] = *(const float4*)(x + (size_t)(m0 + (idx >> 3)) * E_ + (idx & 7) * 4);
        pw[e] = *(const float4*)(W + (size_t)(idx >> 5) * C_ + (idx & 31) * 4);
    }
#pragma unroll
    for (int e = 0; e < 4; e++) {
        int idx = tid + e * 256;
        *(float4*)(&Xs[(idx >> 3) * 36 + (idx & 7) * 4])   = tfr4(px[e]);
        *(float4*)(&Ws[(idx >> 5) * 132 + (idx & 31) * 4]) = tfr4(pw[e]);
    }
    __syncthreads();

    for (int it = 0; it < 32; it++) {
        if (it < 31) {
            const int k0 = (it + 1) * 32;
#pragma unroll
            for (int e = 0; e < 4; e++) {
                int idx = tid + e * 256;
                px[e] = *(const float4*)(x + (size_t)(m0 + (idx >> 3)) * E_ + k0 + (idx & 7) * 4);
                pw[e] = *(const float4*)(W + (size_t)(k0 + (idx >> 5)) * C_ + (idx & 31) * 4);
            }
        }

#pragma unroll
        for (int ks = 0; ks < 4; ks++) {
            const int c0 = ks * 8 + tig;
            uint32_t a[2][4];
#pragma unroll
            for (int mt = 0; mt < 2; mt++) {
                int r0 = wm * 32 + mt * 16 + gid;
                a[mt][0] = U_(Xs[r0 * 36 + c0]);
                a[mt][1] = U_(Xs[(r0 + 8) * 36 + c0]);
                a[mt][2] = U_(Xs[r0 * 36 + c0 + 4]);
                a[mt][3] = U_(Xs[(r0 + 8) * 36 + c0 + 4]);
            }
#pragma unroll
            for (int nt = 0; nt < 8; nt++) {
                int n = wn * 64 + nt * 8 + gid;
                uint32_t b0 = U_(Ws[(ks * 8 + tig) * 132 + n]);
                uint32_t b1 = U_(Ws[(ks * 8 + tig + 4) * 132 + n]);
#pragma unroll
                for (int mt = 0; mt < 2; mt++)
                    mma8(acc[mt][nt], a[mt], b0, b1);
            }
        }
        __syncthreads();

        if (it < 31) {
#pragma unroll
            for (int e = 0; e < 4; e++) {
                int idx = tid + e * 256;
                *(float4*)(&Xs[(idx >> 3) * 36 + (idx & 7) * 4])   = tfr4(px[e]);
                *(float4*)(&Ws[(idx >> 5) * 132 + (idx & 31) * 4]) = tfr4(pw[e]);
            }
            __syncthreads();
        }
    }

    // epilogue: tf32-round and store
#pragma unroll
    for (int mt = 0; mt < 2; mt++) {
        int r0 = m0 + wm * 32 + mt * 16 + gid;
#pragma unroll
        for (int nt = 0; nt < 8; nt++) {
            int c = wn * 64 + nt * 8 + tig * 2;
            *(float2*)(dst + (size_t)r0 * C_ + c)       = make_float2(tfr(acc[mt][nt][0]), tfr(acc[mt][nt][1]));
            *(float2*)(dst + (size_t)(r0 + 8) * C_ + c) = make_float2(tfr(acc[mt][nt][2]), tfr(acc[mt][nt][3]));
        }
    }
}

// ---------------------------------------------------------------------------
// Kernel 2: causal flash attention, tf32 mma.sync, 2 CTA/SM.
// Pre-rounded operands (pure-copy STS); probs stored tf32-rounded.
// Union buffer: K at stride 132 (conflict-free phase A), V at stride 136
// (conflict-free phase B b-loads: bank = tig*8 + gid, a 32-permutation).
// ---------------------------------------------------------------------------
#define QSD 132
#define KSD 132
#define VSD 136
#define PSD 68
#define ATTN_SMEM_BYTES ((64 * QSD + 64 * VSD + 64 * PSD + 192) * 4)

__global__ __launch_bounds__(256, 2) void attn_mma(float* __restrict__ out)
{
    extern __shared__ float sm[];
    float* Qs   = sm;                    // [64][132]
    float* KV   = sm + 64 * QSD;         // union: K [64][132] / V [64][136]
    float* Ps   = KV + 64 * VSD;         // [64][68]
    float* mrow = Ps + 64 * PSD;
    float* lrow = mrow + 64;
    float* srow = lrow + 64;

    const int tid = threadIdx.x;
    const int wid = tid >> 5, lane = tid & 31, gid = lane >> 2, tig = lane & 3;
    const int wm = wid >> 1, wn = wid & 1;

    // balanced mapping: co-resident pair (bid, bid+148) has qt sum == 31
    const int bb = blockIdx.x;
    int b, qt;
    if (bb < 128) { b = bb >> 5;               qt = 31 - (bb & 31); }
    else          { b = 4 + ((bb - 128) >> 5); qt = ((bb & 31) + 12) & 31; }

    // ---- prologue: copy Q tile + prefetch K[0] (pure copies) ----
    const float4* qg = (const float4*)(g_q + (size_t)(b * T_ + qt * 64) * C_);
    float4 kreg[8];
    {
        const float4* kg = (const float4*)(g_k + (size_t)(b * T_) * C_);
#pragma unroll
        for (int e = 0; e < 8; e++) kreg[e] = kg[tid + e * 256];
    }
#pragma unroll
    for (int e = 0; e < 8; e++) {
        int idx = tid + e * 256;
        *(float4*)(&Qs[(idx >> 5) * QSD + (idx & 31) * 4]) = qg[idx];
    }
    if (tid < 64) { mrow[tid] = -1e30f; lrow[tid] = 0.f; }
    __syncthreads();
#pragma unroll
    for (int e = 0; e < 8; e++) {
        int idx = tid + e * 256;
        *(float4*)(&KV[(idx >> 5) * KSD + (idx & 31) * 4]) = kreg[e];
    }
    __syncthreads();   // K visible

    float o[8][4];
#pragma unroll
    for (int nt = 0; nt < 8; nt++)
#pragma unroll
        for (int i = 0; i < 4; i++) o[nt][i] = 0.f;

    const float scale = 0.08838834764831845f;   // 1/sqrt(128)
    const int r0 = wm * 16 + gid;

    for (int kt = 0; kt <= qt; kt++) {
        // ---- issue V[kt] LDG (consumed after sync c) ----
        float4 vreg[8];
        {
            const float4* vg = (const float4*)(g_v + (size_t)(b * T_ + kt * 64) * C_);
#pragma unroll
            for (int e = 0; e < 8; e++) vreg[e] = vg[tid + e * 256];
        }

        // ---- phase A: S = Q @ K^T ----
        float s[4][4];
#pragma unroll
        for (int nt = 0; nt < 4; nt++)
#pragma unroll
            for (int i = 0; i < 4; i++) s[nt][i] = 0.f;

#pragma unroll 4
        for (int ks = 0; ks < 16; ks++) {
            const int c0 = ks * 8 + tig;
            uint32_t a[4];
            a[0] = U_(Qs[r0 * QSD + c0]);
            a[1] = U_(Qs[(r0 + 8) * QSD + c0]);
            a[2] = U_(Qs[r0 * QSD + c0 + 4]);
            a[3] = U_(Qs[(r0 + 8) * QSD + c0 + 4]);
#pragma unroll
            for (int nt = 0; nt < 4; nt++) {
                int n = wn * 32 + nt * 8 + gid;
                uint32_t b0 = U_(KV[n * KSD + c0]);
                uint32_t b1 = U_(KV[n * KSD + c0 + 4]);
                mma8(s[nt], a, b0, b1);
            }
        }

        // scale + causal mask + store S -> Ps
        const bool diag = (kt == qt);
#pragma unroll
        for (int nt = 0; nt < 4; nt++) {
            int kb = wn * 32 + nt * 8 + tig * 2;
            float v0 = s[nt][0] * scale, v1 = s[nt][1] * scale;
            float v2 = s[nt][2] * scale, v3 = s[nt][3] * scale;
            if (diag) {
                if (kb     > r0)     v0 = -1e30f;
                if (kb + 1 > r0)     v1 = -1e30f;
                if (kb     > r0 + 8) v2 = -1e30f;
                if (kb + 1 > r0 + 8) v3 = -1e30f;
            }
            Ps[r0 * PSD + kb]           = v0;
            Ps[r0 * PSD + kb + 1]       = v1;
            Ps[(r0 + 8) * PSD + kb]     = v2;
            Ps[(r0 + 8) * PSD + kb + 1] = v3;
        }
        __syncthreads();   // (c) Ps complete; K reads done

        // ---- STS V at stride 136 (pure copy; overwrites K in union) ----
#pragma unroll
        for (int e = 0; e < 8; e++) {
            int idx = tid + e * 256;
            *(float4*)(&KV[(idx >> 5) * VSD + (idx & 31) * 4]) = vreg[e];
        }

        // ---- issue K[kt+1] LDG (consumed after phase B) ----
        if (kt < qt) {
            const float4* kg = (const float4*)(g_k + (size_t)(b * T_ + (kt + 1) * 64) * C_);
#pragma unroll
            for (int e = 0; e < 8; e++) kreg[e] = kg[tid + e * 256];
        }

        // ---- online softmax: 4 threads per row; store tf32-rounded probs ----
        {
            int r = tid >> 2, seg = tid & 3;
            float* pr = Ps + r * PSD + seg * 16;
            float4 p0 = *(float4*)(pr), p1 = *(float4*)(pr + 4);
            float4 p2 = *(float4*)(pr + 8), p3 = *(float4*)(pr + 12);
            float mx = fmaxf(fmaxf(fmaxf(p0.x, p0.y), fmaxf(p0.z, p0.w)),
                     fmaxf(fmaxf(fmaxf(p1.x, p1.y), fmaxf(p1.z, p1.w)),
                     fmaxf(fmaxf(fmaxf(p2.x, p2.y), fmaxf(p2.z, p2.w)),
                           fmaxf(fmaxf(p3.x, p3.y), fmaxf(p3.z, p3.w)))));
            mx = fmaxf(mx, __shfl_xor_sync(0xffffffffu, mx, 1));
            mx = fmaxf(mx, __shfl_xor_sync(0xffffffffu, mx, 2));
            float mold = mrow[r];
            float newm = fmaxf(mold, mx);
            float fac  = __expf(mold - newm);
            p0.x = __expf(p0.x - newm); p0.y = __expf(p0.y - newm);
            p0.z = __expf(p0.z - newm); p0.w = __expf(p0.w - newm);
            p1.x = __expf(p1.x - newm); p1.y = __expf(p1.y - newm);
            p1.z = __expf(p1.z - newm); p1.w = __expf(p1.w - newm);
            p2.x = __expf(p2.x - newm); p2.y = __expf(p2.y - newm);
            p2.z = __expf(p2.z - newm); p2.w = __expf(p2.w - newm);
            p3.x = __expf(p3.x - newm); p3.y = __expf(p3.y - newm);
            p3.z = __expf(p3.z - newm); p3.w = __expf(p3.w - newm);
            float sum = (p0.x + p0.y + p0.z + p0.w) + (p1.x + p1.y + p1.z + p1.w)
                      + (p2.x + p2.y + p2.z + p2.w) + (p3.x + p3.y + p3.z + p3.w);
            *(float4*)(pr)      = tfr4(p0);
            *(float4*)(pr + 4)  = tfr4(p1);
            *(float4*)(pr + 8)  = tfr4(p2);
            *(float4*)(pr + 12) = tfr4(p3);
            sum += __shfl_xor_sync(0xffffffffu, sum, 1);
            sum += __shfl_xor_sync(0xffffffffu, sum, 2);
            if (seg == 0) {
                lrow[r] = lrow[r] * fac + sum;
                mrow[r] = newm;
                srow[r] = fac;
            }
        }
        __syncthreads();   // (d) V visible, probs + stats ready

        // ---- rescale accumulators ----
        {
            float f0 = srow[r0], f1 = srow[r0 + 8];
#pragma unroll
            for (int nt = 0; nt < 8; nt++) {
                o[nt][0] *= f0; o[nt][1] *= f0;
                o[nt][2] *= f1; o[nt][3] *= f1;
            }
        }

        // ---- phase B: O += P @ V (V at stride 136, conflict-free) ----
#pragma unroll 2
        for (int ks = 0; ks < 8; ks++) {
            const int c0 = ks * 8 + tig;
            uint32_t a[4];
            a[0] = U_(Ps[r0 * PSD + c0]);
            a[1] = U_(Ps[(r0 + 8) * PSD + c0]);
            a[2] = U_(Ps[r0 * PSD + c0 + 4]);
            a[3] = U_(Ps[(r0 + 8) * PSD + c0 + 4]);
#pragma unroll
            for (int nt = 0; nt < 8; nt++) {
                int n = wn * 64 + nt * 8 + gid;
                uint32_t b0 = U_(KV[(ks * 8 + tig) * VSD + n]);
                uint32_t b1 = U_(KV[(ks * 8 + tig + 4) * VSD + n]);
                mma8(o[nt], a, b0, b1);
            }
        }
        __syncthreads();   // (a) phase B done; KV free

        // ---- STS K[kt+1] (pure copy, stride 132) ----
        if (kt < qt) {
#pragma unroll
            for (int e = 0; e < 8; e++) {
                int idx = tid + e * 256;
                *(float4*)(&KV[(idx >> 5) * KSD + (idx & 31) * 4]) = kreg[e];
            }
        }
        __syncthreads();   // (b) K visible
    }

    // ---- epilogue: normalize and store ----
    {
        float inv0 = 1.f / lrow[r0], inv1 = 1.f / lrow[r0 + 8];
        size_t base = (size_t)(b * T_ + qt * 64);
#pragma unroll
        for (int nt = 0; nt < 8; nt++) {
            int c = wn * 64 + nt * 8 + tig * 2;
            *(float2*)(out + (base + r0) * C_ + c)     = make_float2(o[nt][0] * inv0, o[nt][1] * inv0);
            *(float2*)(out + (base + r0 + 8) * C_ + c) = make_float2(o[nt][2] * inv1, o[nt][3] * inv1);
        }
    }
}

// ---------------------------------------------------------------------------
extern "C" void kernel_launch(void* const* d_in, const int* in_sizes, int n_in,
                              void* d_out, int out_size)
{
    const float* x  = (const float*)d_in[0];
    const float* Wk = (const float*)d_in[1];
    const float* Wq = (const float*)d_in[2];
    const float* Wv = (const float*)d_in[3];
    float* out = (float*)d_out;

    cudaFuncSetAttribute(attn_mma,
                         cudaFuncAttributeMaxDynamicSharedMemorySize,
                         ATTN_SMEM_BYTES);

    dim3 qkv_grid(128, 3);
    qkv_mma<<<qkv_grid, 256>>>(x, Wk, Wq, Wv);

    attn_mma<<<B_ * (T_ / 64), 256, ATTN_SMEM_BYTES>>>(out);
}

// round 11
// speedup vs baseline: 1.4588x; 1.1709x over previous
#include <cuda_runtime.h>
#include <cstdint>

#define B_ 8
#define T_ 2048
#define E_ 1024
#define C_ 128

// Scratch for projected Q, K, V (8 MB each), stored tf32-rounded.
__device__ float g_k[B_ * T_ * C_];
__device__ float g_q[B_ * T_ * C_];
__device__ float g_v[B_ * T_ * C_];

// ---------------------------------------------------------------------------
// helpers
// ---------------------------------------------------------------------------
__device__ __forceinline__ float tfr(float x) {
    uint32_t h; asm("cvt.rna.tf32.f32 %0, %1;" : "=r"(h) : "f"(x));
    return __uint_as_float(h);
}
__device__ __forceinline__ float4 tfr4(float4 v) {
    return make_float4(tfr(v.x), tfr(v.y), tfr(v.z), tfr(v.w));
}
__device__ __forceinline__ void mma8(float* c, const uint32_t* a, uint32_t b0, uint32_t b1) {
    asm volatile("mma.sync.aligned.m16n8k8.row.col.f32.tf32.tf32.f32 "
        "{%0,%1,%2,%3}, {%4,%5,%6,%7}, {%8,%9}, {%0,%1,%2,%3};"
        : "+f"(c[0]), "+f"(c[1]), "+f"(c[2]), "+f"(c[3])
        : "r"(a[0]), "r"(a[1]), "r"(a[2]), "r"(a[3]), "r"(b0), "r"(b1));
}
#define U_(f) __float_as_uint(f)

// ---------------------------------------------------------------------------
// Kernel 1: QKV projection, tf32 mma.sync, double-buffered smem (1 sync/iter).
// M128, BK32, 2 CTA/SM.  Epilogue stores tf32-rounded outputs.
// ---------------------------------------------------------------------------
#define QKV_XS 4608              // 128*36 floats
#define QKV_WS 4224              // 32*132 floats
#define QKV_BUF (QKV_XS + QKV_WS)
#define QKV_SMEM_BYTES (2 * QKV_BUF * 4)

__global__ __launch_bounds__(256, 2) void qkv_mma(
    const float* __restrict__ x, const float* __restrict__ Wk,
    const float* __restrict__ Wq, const float* __restrict__ Wv)
{
    extern __shared__ float qsm[];
    const int w = blockIdx.y;
    const float* __restrict__ W = (w == 0) ? Wk : ((w == 1) ? Wq : Wv);
    float* dst = (w == 0) ? g_k : ((w == 1) ? g_q : g_v);

    const int tid = threadIdx.x;
    const int wid = tid >> 5, lane = tid & 31, gid = lane >> 2, tig = lane & 3;
    const int wm = wid >> 1, wn = wid & 1;
    const int m0 = blockIdx.x * 128;

    float acc[2][8][4];
#pragma unroll
    for (int mt = 0; mt < 2; mt++)
#pragma unroll
        for (int nt = 0; nt < 8; nt++)
#pragma unroll
            for (int i = 0; i < 4; i++) acc[mt][nt][i] = 0.f;

    // preload tile 0 into buffer 0
    {
        float* Xs = qsm;
        float* Ws = qsm + QKV_XS;
#pragma unroll
        for (int e = 0; e < 4; e++) {
            int idx = tid + e * 256;
            float4 xv = *(const float4*)(x + (size_t)(m0 + (idx >> 3)) * E_ + (idx & 7) * 4);
            float4 wv = *(const float4*)(W + (size_t)(idx >> 5) * C_ + (idx & 31) * 4);
            *(float4*)(&Xs[(idx >> 3) * 36 + (idx & 7) * 4])   = tfr4(xv);
            *(float4*)(&Ws[(idx >> 5) * 132 + (idx & 31) * 4]) = tfr4(wv);
        }
    }
    __syncthreads();

    for (int it = 0; it < 32; it++) {
        float* Xs = qsm + (it & 1) * QKV_BUF;
        float* Ws = Xs + QKV_XS;

        float4 px[4], pw[4];
        if (it < 31) {
            const int k0 = (it + 1) * 32;
#pragma unroll
            for (int e = 0; e < 4; e++) {
                int idx = tid + e * 256;
                px[e] = *(const float4*)(x + (size_t)(m0 + (idx >> 3)) * E_ + k0 + (idx & 7) * 4);
                pw[e] = *(const float4*)(W + (size_t)(k0 + (idx >> 5)) * C_ + (idx & 31) * 4);
            }
        }

#pragma unroll
        for (int ks = 0; ks < 4; ks++) {
            const int c0 = ks * 8 + tig;
            uint32_t a[2][4];
#pragma unroll
            for (int mt = 0; mt < 2; mt++) {
                int r0 = wm * 32 + mt * 16 + gid;
                a[mt][0] = U_(Xs[r0 * 36 + c0]);
                a[mt][1] = U_(Xs[(r0 + 8) * 36 + c0]);
                a[mt][2] = U_(Xs[r0 * 36 + c0 + 4]);
                a[mt][3] = U_(Xs[(r0 + 8) * 36 + c0 + 4]);
            }
#pragma unroll
            for (int nt = 0; nt < 8; nt++) {
                int n = wn * 64 + nt * 8 + gid;
                uint32_t b0 = U_(Ws[(ks * 8 + tig) * 132 + n]);
                uint32_t b1 = U_(Ws[(ks * 8 + tig + 4) * 132 + n]);
#pragma unroll
                for (int mt = 0; mt < 2; mt++)
                    mma8(acc[mt][nt], a[mt], b0, b1);
            }
        }

        if (it < 31) {
            float* Xn = qsm + ((it + 1) & 1) * QKV_BUF;
            float* Wn = Xn + QKV_XS;
#pragma unroll
            for (int e = 0; e < 4; e++) {
                int idx = tid + e * 256;
                *(float4*)(&Xn[(idx >> 3) * 36 + (idx & 7) * 4])   = tfr4(px[e]);
                *(float4*)(&Wn[(idx >> 5) * 132 + (idx & 31) * 4]) = tfr4(pw[e]);
            }
        }
        __syncthreads();
    }

    // epilogue: tf32-round and store
#pragma unroll
    for (int mt = 0; mt < 2; mt++) {
        int r0 = m0 + wm * 32 + mt * 16 + gid;
#pragma unroll
        for (int nt = 0; nt < 8; nt++) {
            int c = wn * 64 + nt * 8 + tig * 2;
            *(float2*)(dst + (size_t)r0 * C_ + c)       = make_float2(tfr(acc[mt][nt][0]), tfr(acc[mt][nt][1]));
            *(float2*)(dst + (size_t)(r0 + 8) * C_ + c) = make_float2(tfr(acc[mt][nt][2]), tfr(acc[mt][nt][3]));
        }
    }
}

// ---------------------------------------------------------------------------
// Kernel 2: causal flash attention, 32-query-row x 64-key tiles, 3 CTA/SM.
// 512 CTAs (LPT: heavy q32 first), 256 threads, warps 2(m) x 4(n).
// Same reduction chains as R10 -> numerics identical (canary 4.070836e-4).
// ---------------------------------------------------------------------------
#define AQSD 132
#define AKSD 132
#define AVSD 136
#define APSD 68
#define ATTN_SMEM_FLOATS (32 * AQSD + 64 * AVSD + 32 * APSD + 96)
#define ATTN_SMEM_BYTES (ATTN_SMEM_FLOATS * 4)

__global__ __launch_bounds__(256, 3) void attn_mma(float* __restrict__ out)
{
    extern __shared__ float sm[];
    float* Qs   = sm;                    // [32][132]
    float* KV   = sm + 32 * AQSD;        // union: K [64][132] / V [64][136]
    float* Ps   = KV + 64 * AVSD;        // [32][68]
    float* mrow = Ps + 32 * APSD;        // [32]
    float* lrow = mrow + 32;             // [32]
    float* srow = lrow + 32;             // [32]

    const int tid = threadIdx.x;
    const int wid = tid >> 5, lane = tid & 31, gid = lane >> 2, tig = lane & 3;
    const int wm = wid >> 2, wn = wid & 3;

    // LPT: heaviest query tiles first
    const int q32 = 63 - (blockIdx.x >> 3);
    const int b   = blockIdx.x & 7;
    const int nkt = (q32 >> 1) + 1;      // number of 64-key tiles

    // ---- prologue: copy Q (32x128) and K[0] (64x128), pure copies ----
    {
        const float4* qg = (const float4*)(g_q + (size_t)(b * T_ + q32 * 32) * C_);
#pragma unroll
        for (int e = 0; e < 4; e++) {
            int idx = tid + e * 256;
            *(float4*)(&Qs[(idx >> 5) * AQSD + (idx & 31) * 4]) = qg[idx];
        }
        const float4* kg = (const float4*)(g_k + (size_t)(b * T_) * C_);
#pragma unroll
        for (int e = 0; e < 8; e++) {
            int idx = tid + e * 256;
            *(float4*)(&KV[(idx >> 5) * AKSD + (idx & 31) * 4]) = kg[idx];
        }
    }
    if (tid < 32) { mrow[tid] = -1e30f; lrow[tid] = 0.f; }
    __syncthreads();   // Q + K[0] visible

    float o[4][4];
#pragma unroll
    for (int nt = 0; nt < 4; nt++)
#pragma unroll
        for (int i = 0; i < 4; i++) o[nt][i] = 0.f;

    const float scale = 0.08838834764831845f;   // 1/sqrt(128)
    const int r0 = wm * 16 + gid;

    for (int kt = 0; kt < nkt; kt++) {
        // ---- phase A: S = Q @ K^T  (warp tile 16 rows x 16 keys) ----
        float s[2][4];
#pragma unroll
        for (int nt = 0; nt < 2; nt++)
#pragma unroll
            for (int i = 0; i < 4; i++) s[nt][i] = 0.f;

#pragma unroll 4
        for (int ks = 0; ks < 16; ks++) {
            const int c0 = ks * 8 + tig;
            uint32_t a[4];
            a[0] = U_(Qs[r0 * AQSD + c0]);
            a[1] = U_(Qs[(r0 + 8) * AQSD + c0]);
            a[2] = U_(Qs[r0 * AQSD + c0 + 4]);
            a[3] = U_(Qs[(r0 + 8) * AQSD + c0 + 4]);
#pragma unroll
            for (int nt = 0; nt < 2; nt++) {
                int n = wn * 16 + nt * 8 + gid;
                uint32_t b0 = U_(KV[n * AKSD + c0]);
                uint32_t b1 = U_(KV[n * AKSD + c0 + 4]);
                mma8(s[nt], a, b0, b1);
            }
        }

        // scale + causal mask (global compare, branchless across tiles)
        const int off = kt * 64 - q32 * 32;   // key_global - row_global offset
#pragma unroll
        for (int nt = 0; nt < 2; nt++) {
            int kb = wn * 16 + nt * 8 + tig * 2;
            float v0 = s[nt][0] * scale, v1 = s[nt][1] * scale;
            float v2 = s[nt][2] * scale, v3 = s[nt][3] * scale;
            if (kb + off     > r0)     v0 = -1e30f;
            if (kb + 1 + off > r0)     v1 = -1e30f;
            if (kb + off     > r0 + 8) v2 = -1e30f;
            if (kb + 1 + off > r0 + 8) v3 = -1e30f;
            Ps[r0 * APSD + kb]           = v0;
            Ps[r0 * APSD + kb + 1]       = v1;
            Ps[(r0 + 8) * APSD + kb]     = v2;
            Ps[(r0 + 8) * APSD + kb + 1] = v3;
        }
        __syncthreads();   // (c) Ps ready; K reads done

        // ---- V: LDG now, softmax in between (hides latency), STS after ----
        float4 vreg[8];
        {
            const float4* vg = (const float4*)(g_v + (size_t)(b * T_ + kt * 64) * C_);
#pragma unroll
            for (int e = 0; e < 8; e++) vreg[e] = vg[tid + e * 256];
        }

        // ---- online softmax: 32 rows, 8 threads/row, tf32-rounded probs ----
        {
            int r = tid >> 3, seg = tid & 7;
            float* pr = Ps + r * APSD + seg * 8;
            float4 p0 = *(float4*)(pr), p1 = *(float4*)(pr + 4);
            float mx = fmaxf(fmaxf(fmaxf(p0.x, p0.y), fmaxf(p0.z, p0.w)),
                             fmaxf(fmaxf(p1.x, p1.y), fmaxf(p1.z, p1.w)));
            mx = fmaxf(mx, __shfl_xor_sync(0xffffffffu, mx, 1));
            mx = fmaxf(mx, __shfl_xor_sync(0xffffffffu, mx, 2));
            mx = fmaxf(mx, __shfl_xor_sync(0xffffffffu, mx, 4));
            float mold = mrow[r];
            float newm = fmaxf(mold, mx);
            float fac  = __expf(mold - newm);
            p0.x = __expf(p0.x - newm); p0.y = __expf(p0.y - newm);
            p0.z = __expf(p0.z - newm); p0.w = __expf(p0.w - newm);
            p1.x = __expf(p1.x - newm); p1.y = __expf(p1.y - newm);
            p1.z = __expf(p1.z - newm); p1.w = __expf(p1.w - newm);
            float sum = (p0.x + p0.y + p0.z + p0.w) + (p1.x + p1.y + p1.z + p1.w);
            *(float4*)(pr)     = tfr4(p0);
            *(float4*)(pr + 4) = tfr4(p1);
            sum += __shfl_xor_sync(0xffffffffu, sum, 1);
            sum += __shfl_xor_sync(0xffffffffu, sum, 2);
            sum += __shfl_xor_sync(0xffffffffu, sum, 4);
            if (seg == 0) {
                lrow[r] = lrow[r] * fac + sum;
                mrow[r] = newm;
                srow[r] = fac;
            }
        }

        // ---- STS V at stride 136 (overwrites K in union) ----
#pragma unroll
        for (int e = 0; e < 8; e++) {
            int idx = tid + e * 256;
            *(float4*)(&KV[(idx >> 5) * AVSD + (idx & 31) * 4]) = vreg[e];
        }
        __syncthreads();   // (d) V + probs + stats visible

        // ---- rescale accumulators ----
        {
            float f0 = srow[r0], f1 = srow[r0 + 8];
#pragma unroll
            for (int nt = 0; nt < 4; nt++) {
                o[nt][0] *= f0; o[nt][1] *= f0;
                o[nt][2] *= f1; o[nt][3] *= f1;
            }
        }

        // ---- phase B: O += P @ V  (warp covers 32 d-cols, all 64 keys) ----
#pragma unroll 2
        for (int ks = 0; ks < 8; ks++) {
            const int c0 = ks * 8 + tig;
            uint32_t a[4];
            a[0] = U_(Ps[r0 * APSD + c0]);
            a[1] = U_(Ps[(r0 + 8) * APSD + c0]);
            a[2] = U_(Ps[r0 * APSD + c0 + 4]);
            a[3] = U_(Ps[(r0 + 8) * APSD + c0 + 4]);
#pragma unroll
            for (int nt = 0; nt < 4; nt++) {
                int n = wn * 32 + nt * 8 + gid;
                uint32_t b0 = U_(KV[(ks * 8 + tig) * AVSD + n]);
                uint32_t b1 = U_(KV[(ks * 8 + tig + 4) * AVSD + n]);
                mma8(o[nt], a, b0, b1);
            }
        }
        __syncthreads();   // (a) phase B done; KV free

        // ---- load K[kt+1] (stride 132) ----
        if (kt + 1 < nkt) {
            const float4* kg = (const float4*)(g_k + (size_t)(b * T_ + (kt + 1) * 64) * C_);
#pragma unroll
            for (int e = 0; e < 8; e++) {
                int idx = tid + e * 256;
                *(float4*)(&KV[(idx >> 5) * AKSD + (idx & 31) * 4]) = kg[idx];
            }
        }
        __syncthreads();   // (b) K visible
    }

    // ---- epilogue: normalize and store ----
    {
        float inv0 = 1.f / lrow[r0], inv1 = 1.f / lrow[r0 + 8];
        size_t base = (size_t)(b * T_ + q32 * 32);
#pragma unroll
        for (int nt = 0; nt < 4; nt++) {
            int c = wn * 32 + nt * 8 + tig * 2;
            *(float2*)(out + (base + r0) * C_ + c)     = make_float2(o[nt][0] * inv0, o[nt][1] * inv0);
            *(float2*)(out + (base + r0 + 8) * C_ + c) = make_float2(o[nt][2] * inv1, o[nt][3] * inv1);
        }
    }
}

// ---------------------------------------------------------------------------
extern "C" void kernel_launch(void* const* d_in, const int* in_sizes, int n_in,
                              void* d_out, int out_size)
{
    const float* x  = (const float*)d_in[0];
    const float* Wk = (const float*)d_in[1];
    const float* Wq = (const float*)d_in[2];
    const float* Wv = (const float*)d_in[3];
    float* out = (float*)d_out;

    cudaFuncSetAttribute(qkv_mma,
                         cudaFuncAttributeMaxDynamicSharedMemorySize,
                         QKV_SMEM_BYTES);
    cudaFuncSetAttribute(attn_mma,
                         cudaFuncAttributeMaxDynamicSharedMemorySize,
                         ATTN_SMEM_BYTES);

    dim3 qkv_grid(128, 3);
    qkv_mma<<<qkv_grid, 256, QKV_SMEM_BYTES>>>(x, Wk, Wq, Wv);

    attn_mma<<<B_ * (T_ / 32), 256, ATTN_SMEM_BYTES>>>(out);
}

// round 13
// speedup vs baseline: 1.5755x; 1.0800x over previous
#include <cuda_runtime.h>
#include <cstdint>

#define B_ 8
#define T_ 2048
#define E_ 1024
#define C_ 128

// Scratch for projected Q, K, V (8 MB each), stored tf32-rounded.
__device__ float g_k[B_ * T_ * C_];
__device__ float g_q[B_ * T_ * C_];
__device__ float g_v[B_ * T_ * C_];

// ---------------------------------------------------------------------------
// helpers
// ---------------------------------------------------------------------------
__device__ __forceinline__ float tfr(float x) {
    uint32_t h; asm("cvt.rna.tf32.f32 %0, %1;" : "=r"(h) : "f"(x));
    return __uint_as_float(h);
}
__device__ __forceinline__ float4 tfr4(float4 v) {
    return make_float4(tfr(v.x), tfr(v.y), tfr(v.z), tfr(v.w));
}
__device__ __forceinline__ void mma8(float* c, const uint32_t* a, uint32_t b0, uint32_t b1) {
    asm volatile("mma.sync.aligned.m16n8k8.row.col.f32.tf32.tf32.f32 "
        "{%0,%1,%2,%3}, {%4,%5,%6,%7}, {%8,%9}, {%0,%1,%2,%3};"
        : "+f"(c[0]), "+f"(c[1]), "+f"(c[2]), "+f"(c[3])
        : "r"(a[0]), "r"(a[1]), "r"(a[2]), "r"(a[3]), "r"(b0), "r"(b1));
}
__device__ __forceinline__ uint32_t sma(const void* p) {
    return (uint32_t)__cvta_generic_to_shared(p);
}
#define CP_ASYNC16(dst, src) \
    asm volatile("cp.async.cg.shared.global [%0], [%1], 16;" :: "r"(dst), "l"(src) : "memory")
#define CP_COMMIT()  asm volatile("cp.async.commit_group;" ::: "memory")
#define CP_WAIT0()   asm volatile("cp.async.wait_group 0;" ::: "memory")
#define U_(f) __float_as_uint(f)

// ---------------------------------------------------------------------------
// Kernel 1: QKV projection, tf32 mma.sync, double-buffered smem (1 sync/iter).
// M128, BK32, 2 CTA/SM.  Epilogue stores tf32-rounded outputs.  (R11, proven)
// ---------------------------------------------------------------------------
#define QKV_XS 4608              // 128*36 floats
#define QKV_WS 4224              // 32*132 floats
#define QKV_BUF (QKV_XS + QKV_WS)
#define QKV_SMEM_BYTES (2 * QKV_BUF * 4)

__global__ __launch_bounds__(256, 2) void qkv_mma(
    const float* __restrict__ x, const float* __restrict__ Wk,
    const float* __restrict__ Wq, const float* __restrict__ Wv)
{
    extern __shared__ float qsm[];
    const int w = blockIdx.y;
    const float* __restrict__ W = (w == 0) ? Wk : ((w == 1) ? Wq : Wv);
    float* dst = (w == 0) ? g_k : ((w == 1) ? g_q : g_v);

    const int tid = threadIdx.x;
    const int wid = tid >> 5, lane = tid & 31, gid = lane >> 2, tig = lane & 3;
    const int wm = wid >> 1, wn = wid & 1;
    const int m0 = blockIdx.x * 128;

    float acc[2][8][4];
#pragma unroll
    for (int mt = 0; mt < 2; mt++)
#pragma unroll
        for (int nt = 0; nt < 8; nt++)
#pragma unroll
            for (int i = 0; i < 4; i++) acc[mt][nt][i] = 0.f;

    {
        float* Xs = qsm;
        float* Ws = qsm + QKV_XS;
#pragma unroll
        for (int e = 0; e < 4; e++) {
            int idx = tid + e * 256;
            float4 xv = *(const float4*)(x + (size_t)(m0 + (idx >> 3)) * E_ + (idx & 7) * 4);
            float4 wv = *(const float4*)(W + (size_t)(idx >> 5) * C_ + (idx & 31) * 4);
            *(float4*)(&Xs[(idx >> 3) * 36 + (idx & 7) * 4])   = tfr4(xv);
            *(float4*)(&Ws[(idx >> 5) * 132 + (idx & 31) * 4]) = tfr4(wv);
        }
    }
    __syncthreads();

    for (int it = 0; it < 32; it++) {
        float* Xs = qsm + (it & 1) * QKV_BUF;
        float* Ws = Xs + QKV_XS;

        float4 px[4], pw[4];
        if (it < 31) {
            const int k0 = (it + 1) * 32;
#pragma unroll
            for (int e = 0; e < 4; e++) {
                int idx = tid + e * 256;
                px[e] = *(const float4*)(x + (size_t)(m0 + (idx >> 3)) * E_ + k0 + (idx & 7) * 4);
                pw[e] = *(const float4*)(W + (size_t)(k0 + (idx >> 5)) * C_ + (idx & 31) * 4);
            }
        }

#pragma unroll
        for (int ks = 0; ks < 4; ks++) {
            const int c0 = ks * 8 + tig;
            uint32_t a[2][4];
#pragma unroll
            for (int mt = 0; mt < 2; mt++) {
                int r0 = wm * 32 + mt * 16 + gid;
                a[mt][0] = U_(Xs[r0 * 36 + c0]);
                a[mt][1] = U_(Xs[(r0 + 8) * 36 + c0]);
                a[mt][2] = U_(Xs[r0 * 36 + c0 + 4]);
                a[mt][3] = U_(Xs[(r0 + 8) * 36 + c0 + 4]);
            }
#pragma unroll
            for (int nt = 0; nt < 8; nt++) {
                int n = wn * 64 + nt * 8 + gid;
                uint32_t b0 = U_(Ws[(ks * 8 + tig) * 132 + n]);
                uint32_t b1 = U_(Ws[(ks * 8 + tig + 4) * 132 + n]);
#pragma unroll
                for (int mt = 0; mt < 2; mt++)
                    mma8(acc[mt][nt], a[mt], b0, b1);
            }
        }

        if (it < 31) {
            float* Xn = qsm + ((it + 1) & 1) * QKV_BUF;
            float* Wn = Xn + QKV_XS;
#pragma unroll
            for (int e = 0; e < 4; e++) {
                int idx = tid + e * 256;
                *(float4*)(&Xn[(idx >> 3) * 36 + (idx & 7) * 4])   = tfr4(px[e]);
                *(float4*)(&Wn[(idx >> 5) * 132 + (idx & 31) * 4]) = tfr4(pw[e]);
            }
        }
        __syncthreads();
    }

#pragma unroll
    for (int mt = 0; mt < 2; mt++) {
        int r0 = m0 + wm * 32 + mt * 16 + gid;
#pragma unroll
        for (int nt = 0; nt < 8; nt++) {
            int c = wn * 64 + nt * 8 + tig * 2;
            *(float2*)(dst + (size_t)r0 * C_ + c)       = make_float2(tfr(acc[mt][nt][0]), tfr(acc[mt][nt][1]));
            *(float2*)(dst + (size_t)(r0 + 8) * C_ + c) = make_float2(tfr(acc[mt][nt][2]), tfr(acc[mt][nt][3]));
        }
    }
}

// ---------------------------------------------------------------------------
// Kernel 2: causal flash attention, 32-row x 64-key tiles, 3 CTA/SM,
// K/V staged via cp.async (zero register cost; V hidden under softmax).
// ---------------------------------------------------------------------------
#define AQSD 132
#define AKSD 132
#define AVSD 136
#define APSD 68
#define ATTN_SMEM_FLOATS (32 * AQSD + 64 * AVSD + 32 * APSD + 96)
#define ATTN_SMEM_BYTES (ATTN_SMEM_FLOATS * 4)

__global__ __launch_bounds__(256, 3) void attn_mma(float* __restrict__ out)
{
    extern __shared__ float sm[];
    float* Qs   = sm;                    // [32][132]
    float* KV   = sm + 32 * AQSD;        // union: K [64][132] / V [64][136]
    float* Ps   = KV + 64 * AVSD;        // [32][68]
    float* mrow = Ps + 32 * APSD;        // [32]
    float* lrow = mrow + 32;             // [32]
    float* srow = lrow + 32;             // [32]

    const int tid = threadIdx.x;
    const int wid = tid >> 5, lane = tid & 31, gid = lane >> 2, tig = lane & 3;
    const int wm = wid >> 2, wn = wid & 3;

    // LPT: heaviest query tiles first
    const int q32 = 63 - (blockIdx.x >> 3);
    const int b   = blockIdx.x & 7;
    const int nkt = (q32 >> 1) + 1;      // number of 64-key tiles

    // ---- prologue: copy Q (32x128) and K[0] (64x128) ----
    {
        const float4* qg = (const float4*)(g_q + (size_t)(b * T_ + q32 * 32) * C_);
#pragma unroll
        for (int e = 0; e < 4; e++) {
            int idx = tid + e * 256;
            *(float4*)(&Qs[(idx >> 5) * AQSD + (idx & 31) * 4]) = qg[idx];
        }
        const float* kg = g_k + (size_t)(b * T_) * C_;
#pragma unroll
        for (int e = 0; e < 8; e++) {
            int idx = tid + e * 256;
            CP_ASYNC16(sma(&KV[(idx >> 5) * AKSD + (idx & 31) * 4]),
                       kg + (size_t)idx * 4);
        }
        CP_COMMIT();
    }
    if (tid < 32) { mrow[tid] = -1e30f; lrow[tid] = 0.f; }
    CP_WAIT0();
    __syncthreads();   // Q + K[0] visible

    float o[4][4];
#pragma unroll
    for (int nt = 0; nt < 4; nt++)
#pragma unroll
        for (int i = 0; i < 4; i++) o[nt][i] = 0.f;

    const float scale = 0.08838834764831845f;   // 1/sqrt(128)
    const int r0 = wm * 16 + gid;

    for (int kt = 0; kt < nkt; kt++) {
        // ---- phase A: S = Q @ K^T  (warp tile 16 rows x 16 keys) ----
        float s[2][4];
#pragma unroll
        for (int nt = 0; nt < 2; nt++)
#pragma unroll
            for (int i = 0; i < 4; i++) s[nt][i] = 0.f;

#pragma unroll 4
        for (int ks = 0; ks < 16; ks++) {
            const int c0 = ks * 8 + tig;
            uint32_t a[4];
            a[0] = U_(Qs[r0 * AQSD + c0]);
            a[1] = U_(Qs[(r0 + 8) * AQSD + c0]);
            a[2] = U_(Qs[r0 * AQSD + c0 + 4]);
            a[3] = U_(Qs[(r0 + 8) * AQSD + c0 + 4]);
#pragma unroll
            for (int nt = 0; nt < 2; nt++) {
                int n = wn * 16 + nt * 8 + gid;
                uint32_t b0 = U_(KV[n * AKSD + c0]);
                uint32_t b1 = U_(KV[n * AKSD + c0 + 4]);
                mma8(s[nt], a, b0, b1);
            }
        }

        // scale + causal mask (global compare, branchless across tiles)
        const int off = kt * 64 - q32 * 32;
#pragma unroll
        for (int nt = 0; nt < 2; nt++) {
            int kb = wn * 16 + nt * 8 + tig * 2;
            float v0 = s[nt][0] * scale, v1 = s[nt][1] * scale;
            float v2 = s[nt][2] * scale, v3 = s[nt][3] * scale;
            if (kb + off     > r0)     v0 = -1e30f;
            if (kb + 1 + off > r0)     v1 = -1e30f;
            if (kb + off     > r0 + 8) v2 = -1e30f;
            if (kb + 1 + off > r0 + 8) v3 = -1e30f;
            Ps[r0 * APSD + kb]           = v0;
            Ps[r0 * APSD + kb + 1]       = v1;
            Ps[(r0 + 8) * APSD + kb]     = v2;
            Ps[(r0 + 8) * APSD + kb + 1] = v3;
        }
        __syncthreads();   // (c) Ps ready; phase-A K reads done -> union free

        // ---- V[kt] via cp.async (hidden under softmax) ----
        {
            const float* vg = g_v + (size_t)(b * T_ + kt * 64) * C_;
#pragma unroll
            for (int e = 0; e < 8; e++) {
                int idx = tid + e * 256;
                CP_ASYNC16(sma(&KV[(idx >> 5) * AVSD + (idx & 31) * 4]),
                           vg + (size_t)idx * 4);
            }
            CP_COMMIT();
        }

        // ---- online softmax: 32 rows, 8 threads/row, tf32-rounded probs ----
        {
            int r = tid >> 3, seg = tid & 7;
            float* pr = Ps + r * APSD + seg * 8;
            float4 p0 = *(float4*)(pr), p1 = *(float4*)(pr + 4);
            float mx = fmaxf(fmaxf(fmaxf(p0.x, p0.y), fmaxf(p0.z, p0.w)),
                             fmaxf(fmaxf(p1.x, p1.y), fmaxf(p1.z, p1.w)));
            mx = fmaxf(mx, __shfl_xor_sync(0xffffffffu, mx, 1));
            mx = fmaxf(mx, __shfl_xor_sync(0xffffffffu, mx, 2));
            mx = fmaxf(mx, __shfl_xor_sync(0xffffffffu, mx, 4));
            float mold = mrow[r];
            float newm = fmaxf(mold, mx);
            float fac  = __expf(mold - newm);
            p0.x = __expf(p0.x - newm); p0.y = __expf(p0.y - newm);
            p0.z = __expf(p0.z - newm); p0.w = __expf(p0.w - newm);
            p1.x = __expf(p1.x - newm); p1.y = __expf(p1.y - newm);
            p1.z = __expf(p1.z - newm); p1.w = __expf(p1.w - newm);
            float sum = (p0.x + p0.y + p0.z + p0.w) + (p1.x + p1.y + p1.z + p1.w);
            *(float4*)(pr)     = tfr4(p0);
            *(float4*)(pr + 4) = tfr4(p1);
            sum += __shfl_xor_sync(0xffffffffu, sum, 1);
            sum += __shfl_xor_sync(0xffffffffu, sum, 2);
            sum += __shfl_xor_sync(0xffffffffu, sum, 4);
            if (seg == 0) {
                lrow[r] = lrow[r] * fac + sum;
                mrow[r] = newm;
                srow[r] = fac;
            }
        }
        CP_WAIT0();
        __syncthreads();   // (d) V + probs + stats visible

        // ---- rescale accumulators ----
        {
            float f0 = srow[r0], f1 = srow[r0 + 8];
#pragma unroll
            for (int nt = 0; nt < 4; nt++) {
                o[nt][0] *= f0; o[nt][1] *= f0;
                o[nt][2] *= f1; o[nt][3] *= f1;
            }
        }

        // ---- phase B: O += P @ V  (warp covers 32 d-cols, all 64 keys) ----
#pragma unroll 2
        for (int ks = 0; ks < 8; ks++) {
            const int c0 = ks * 8 + tig;
            uint32_t a[4];
            a[0] = U_(Ps[r0 * APSD + c0]);
            a[1] = U_(Ps[(r0 + 8) * APSD + c0]);
            a[2] = U_(Ps[r0 * APSD + c0 + 4]);
            a[3] = U_(Ps[(r0 + 8) * APSD + c0 + 4]);
#pragma unroll
            for (int nt = 0; nt < 4; nt++) {
                int n = wn * 32 + nt * 8 + gid;
                uint32_t b0 = U_(KV[(ks * 8 + tig) * AVSD + n]);
                uint32_t b1 = U_(KV[(ks * 8 + tig + 4) * AVSD + n]);
                mma8(o[nt], a, b0, b1);
            }
        }
        __syncthreads();   // (a) phase B done; union free

        // ---- K[kt+1] via cp.async ----
        if (kt + 1 < nkt) {
            const float* kg = g_k + (size_t)(b * T_ + (kt + 1) * 64) * C_;
#pragma unroll
            for (int e = 0; e < 8; e++) {
                int idx = tid + e * 256;
                CP_ASYNC16(sma(&KV[(idx >> 5) * AKSD + (idx & 31) * 4]),
                           kg + (size_t)idx * 4);
            }
            CP_COMMIT();
            CP_WAIT0();
        }
        __syncthreads();   // (b) K visible
    }

    // ---- epilogue: normalize and store ----
    {
        float inv0 = 1.f / lrow[r0], inv1 = 1.f / lrow[r0 + 8];
        size_t base = (size_t)(b * T_ + q32 * 32);
#pragma unroll
        for (int nt = 0; nt < 4; nt++) {
            int c = wn * 32 + nt * 8 + tig * 2;
            *(float2*)(out + (base + r0) * C_ + c)     = make_float2(o[nt][0] * inv0, o[nt][1] * inv0);
            *(float2*)(out + (base + r0 + 8) * C_ + c) = make_float2(o[nt][2] * inv1, o[nt][3] * inv1);
        }
    }
}

// ---------------------------------------------------------------------------
extern "C" void kernel_launch(void* const* d_in, const int* in_sizes, int n_in,
                              void* d_out, int out_size)
{
    const float* x  = (const float*)d_in[0];
    const float* Wk = (const float*)d_in[1];
    const float* Wq = (const float*)d_in[2];
    const float* Wv = (const float*)d_in[3];
    float* out = (float*)d_out;

    cudaFuncSetAttribute(qkv_mma,
                         cudaFuncAttributeMaxDynamicSharedMemorySize,
                         QKV_SMEM_BYTES);
    cudaFuncSetAttribute(attn_mma,
                         cudaFuncAttributeMaxDynamicSharedMemorySize,
                         ATTN_SMEM_BYTES);

    dim3 qkv_grid(128, 3);
    qkv_mma<<<qkv_grid, 256, QKV_SMEM_BYTES>>>(x, Wk, Wq, Wv);

    attn_mma<<<B_ * (T_ / 32), 256, ATTN_SMEM_BYTES>>>(out);
}

// round 16
// speedup vs baseline: 1.6351x; 1.0379x over previous
#include <cuda_runtime.h>
#include <cstdint>

#define B_ 8
#define T_ 2048
#define E_ 1024
#define C_ 128

// Scratch for projected Q, K, V (8 MB each), stored tf32-rounded.
__device__ float g_k[B_ * T_ * C_];
__device__ float g_q[B_ * T_ * C_];
__device__ float g_v[B_ * T_ * C_];
// Split-K partials: 8 batches x 32 heavy q-tiles x 2 splits x (32x128 O)
__device__ float g_po[8 * 32 * 2 * 32 * 128];
__device__ float g_pm[8 * 32 * 2 * 32];
__device__ float g_pl[8 * 32 * 2 * 32];

// ---------------------------------------------------------------------------
// helpers
// ---------------------------------------------------------------------------
__device__ __forceinline__ float tfr(float x) {
    uint32_t h; asm("cvt.rna.tf32.f32 %0, %1;" : "=r"(h) : "f"(x));
    return __uint_as_float(h);
}
__device__ __forceinline__ float4 tfr4(float4 v) {
    return make_float4(tfr(v.x), tfr(v.y), tfr(v.z), tfr(v.w));
}
__device__ __forceinline__ void mma8(float* c, const uint32_t* a, uint32_t b0, uint32_t b1) {
    asm volatile("mma.sync.aligned.m16n8k8.row.col.f32.tf32.tf32.f32 "
        "{%0,%1,%2,%3}, {%4,%5,%6,%7}, {%8,%9}, {%0,%1,%2,%3};"
        : "+f"(c[0]), "+f"(c[1]), "+f"(c[2]), "+f"(c[3])
        : "r"(a[0]), "r"(a[1]), "r"(a[2]), "r"(a[3]), "r"(b0), "r"(b1));
}
__device__ __forceinline__ uint32_t sma(const void* p) {
    return (uint32_t)__cvta_generic_to_shared(p);
}
#define CP_ASYNC16(dst, src) \
    asm volatile("cp.async.cg.shared.global [%0], [%1], 16;" :: "r"(dst), "l"(src) : "memory")
#define CP_COMMIT()  asm volatile("cp.async.commit_group;" ::: "memory")
#define CP_WAIT0()   asm volatile("cp.async.wait_group 0;" ::: "memory")
#define U_(f) __float_as_uint(f)

// ---------------------------------------------------------------------------
// Kernel 1: QKV projection (R13, proven).
// ---------------------------------------------------------------------------
#define QKV_XS 4608
#define QKV_WS 4224
#define QKV_BUF (QKV_XS + QKV_WS)
#define QKV_SMEM_BYTES (2 * QKV_BUF * 4)

__global__ __launch_bounds__(256, 2) void qkv_mma(
    const float* __restrict__ x, const float* __restrict__ Wk,
    const float* __restrict__ Wq, const float* __restrict__ Wv)
{
    extern __shared__ float qsm[];
    const int w = blockIdx.y;
    const float* __restrict__ W = (w == 0) ? Wk : ((w == 1) ? Wq : Wv);
    float* dst = (w == 0) ? g_k : ((w == 1) ? g_q : g_v);

    const int tid = threadIdx.x;
    const int wid = tid >> 5, lane = tid & 31, gid = lane >> 2, tig = lane & 3;
    const int wm = wid >> 1, wn = wid & 1;
    const int m0 = blockIdx.x * 128;

    float acc[2][8][4];
#pragma unroll
    for (int mt = 0; mt < 2; mt++)
#pragma unroll
        for (int nt = 0; nt < 8; nt++)
#pragma unroll
            for (int i = 0; i < 4; i++) acc[mt][nt][i] = 0.f;

    {
        float* Xs = qsm;
        float* Ws = qsm + QKV_XS;
#pragma unroll
        for (int e = 0; e < 4; e++) {
            int idx = tid + e * 256;
            float4 xv = *(const float4*)(x + (size_t)(m0 + (idx >> 3)) * E_ + (idx & 7) * 4);
            float4 wv = *(const float4*)(W + (size_t)(idx >> 5) * C_ + (idx & 31) * 4);
            *(float4*)(&Xs[(idx >> 3) * 36 + (idx & 7) * 4])   = tfr4(xv);
            *(float4*)(&Ws[(idx >> 5) * 132 + (idx & 31) * 4]) = tfr4(wv);
        }
    }
    __syncthreads();

    for (int it = 0; it < 32; it++) {
        float* Xs = qsm + (it & 1) * QKV_BUF;
        float* Ws = Xs + QKV_XS;

        float4 px[4], pw[4];
        if (it < 31) {
            const int k0 = (it + 1) * 32;
#pragma unroll
            for (int e = 0; e < 4; e++) {
                int idx = tid + e * 256;
                px[e] = *(const float4*)(x + (size_t)(m0 + (idx >> 3)) * E_ + k0 + (idx & 7) * 4);
                pw[e] = *(const float4*)(W + (size_t)(k0 + (idx >> 5)) * C_ + (idx & 31) * 4);
            }
        }

#pragma unroll
        for (int ks = 0; ks < 4; ks++) {
            const int c0 = ks * 8 + tig;
            uint32_t a[2][4];
#pragma unroll
            for (int mt = 0; mt < 2; mt++) {
                int r0 = wm * 32 + mt * 16 + gid;
                a[mt][0] = U_(Xs[r0 * 36 + c0]);
                a[mt][1] = U_(Xs[(r0 + 8) * 36 + c0]);
                a[mt][2] = U_(Xs[r0 * 36 + c0 + 4]);
                a[mt][3] = U_(Xs[(r0 + 8) * 36 + c0 + 4]);
            }
#pragma unroll
            for (int nt = 0; nt < 8; nt++) {
                int n = wn * 64 + nt * 8 + gid;
                uint32_t b0 = U_(Ws[(ks * 8 + tig) * 132 + n]);
                uint32_t b1 = U_(Ws[(ks * 8 + tig + 4) * 132 + n]);
#pragma unroll
                for (int mt = 0; mt < 2; mt++)
                    mma8(acc[mt][nt], a[mt], b0, b1);
            }
        }

        if (it < 31) {
            float* Xn = qsm + ((it + 1) & 1) * QKV_BUF;
            float* Wn = Xn + QKV_XS;
#pragma unroll
            for (int e = 0; e < 4; e++) {
                int idx = tid + e * 256;
                *(float4*)(&Xn[(idx >> 3) * 36 + (idx & 7) * 4])   = tfr4(px[e]);
                *(float4*)(&Wn[(idx >> 5) * 132 + (idx & 31) * 4]) = tfr4(pw[e]);
            }
        }
        __syncthreads();
    }

#pragma unroll
    for (int mt = 0; mt < 2; mt++) {
        int r0 = m0 + wm * 32 + mt * 16 + gid;
#pragma unroll
        for (int nt = 0; nt < 8; nt++) {
            int c = wn * 64 + nt * 8 + tig * 2;
            *(float2*)(dst + (size_t)r0 * C_ + c)       = make_float2(tfr(acc[mt][nt][0]), tfr(acc[mt][nt][1]));
            *(float2*)(dst + (size_t)(r0 + 8) * C_ + c) = make_float2(tfr(acc[mt][nt][2]), tfr(acc[mt][nt][3]));
        }
    }
}

// ---------------------------------------------------------------------------
// Kernel 2: causal flash attention with split-K load balancing.
// Per batch: 96 CTAs. i = blockIdx.x>>3, g = i/3, rem = i%3:
//   rem 0/1: q32 = 63-g, split s=rem (heavy tile halved)
//   rem 2:   q32 = 31-g (light tile, whole range)
// Heavy splits write unnormalized partial O + (m,l); merge kernel combines.
// ---------------------------------------------------------------------------
#define AQSD 132
#define AKSD 132
#define AVSD 136
#define APSD 68
#define ATTN_SMEM_FLOATS (32 * AQSD + 64 * AVSD + 32 * APSD + 96)
#define ATTN_SMEM_BYTES (ATTN_SMEM_FLOATS * 4)

__global__ __launch_bounds__(256, 3) void attn_mma(float* __restrict__ out)
{
    extern __shared__ float sm[];
    float* Qs   = sm;
    float* KV   = sm + 32 * AQSD;
    float* Ps   = KV + 64 * AVSD;
    float* mrow = Ps + 32 * APSD;
    float* lrow = mrow + 32;
    float* srow = lrow + 32;

    const int tid = threadIdx.x;
    const int wid = tid >> 5, lane = tid & 31, gid = lane >> 2, tig = lane & 3;
    const int wm = wid >> 2, wn = wid & 3;

    // work mapping (heavy-first)
    const int i = blockIdx.x >> 3;
    const int b = blockIdx.x & 7;
    const int g = i / 3, rem = i - 3 * g;
    int q32, sp = 0, isplit = 0;
    if (rem == 2) { q32 = 31 - g; }
    else          { q32 = 63 - g; sp = rem; isplit = 1; }
    const int nkt = (q32 >> 1) + 1;
    int kt0 = 0, kt1 = nkt;
    if (isplit) {
        const int h = (nkt + 1) >> 1;
        kt0 = sp ? h : 0;
        kt1 = sp ? nkt : h;
    }

    // ---- prologue: copy Q (32x128) and K[kt0] (64x128) ----
    {
        const float4* qg = (const float4*)(g_q + (size_t)(b * T_ + q32 * 32) * C_);
#pragma unroll
        for (int e = 0; e < 4; e++) {
            int idx = tid + e * 256;
            *(float4*)(&Qs[(idx >> 5) * AQSD + (idx & 31) * 4]) = qg[idx];
        }
        const float* kg = g_k + (size_t)(b * T_ + kt0 * 64) * C_;
#pragma unroll
        for (int e = 0; e < 8; e++) {
            int idx = tid + e * 256;
            CP_ASYNC16(sma(&KV[(idx >> 5) * AKSD + (idx & 31) * 4]),
                       kg + (size_t)idx * 4);
        }
        CP_COMMIT();
    }
    if (tid < 32) { mrow[tid] = -1e30f; lrow[tid] = 0.f; }
    CP_WAIT0();
    __syncthreads();

    float o[4][4];
#pragma unroll
    for (int nt = 0; nt < 4; nt++)
#pragma unroll
        for (int i2 = 0; i2 < 4; i2++) o[nt][i2] = 0.f;

    const float scale = 0.08838834764831845f;
    const int r0 = wm * 16 + gid;

    for (int kt = kt0; kt < kt1; kt++) {
        // ---- phase A: S = Q @ K^T ----
        float s[2][4];
#pragma unroll
        for (int nt = 0; nt < 2; nt++)
#pragma unroll
            for (int i2 = 0; i2 < 4; i2++) s[nt][i2] = 0.f;

#pragma unroll 4
        for (int ks = 0; ks < 16; ks++) {
            const int c0 = ks * 8 + tig;
            uint32_t a[4];
            a[0] = U_(Qs[r0 * AQSD + c0]);
            a[1] = U_(Qs[(r0 + 8) * AQSD + c0]);
            a[2] = U_(Qs[r0 * AQSD + c0 + 4]);
            a[3] = U_(Qs[(r0 + 8) * AQSD + c0 + 4]);
#pragma unroll
            for (int nt = 0; nt < 2; nt++) {
                int n = wn * 16 + nt * 8 + gid;
                uint32_t b0 = U_(KV[n * AKSD + c0]);
                uint32_t b1 = U_(KV[n * AKSD + c0 + 4]);
                mma8(s[nt], a, b0, b1);
            }
        }

        // scale + causal mask
        const int off = kt * 64 - q32 * 32;
#pragma unroll
        for (int nt = 0; nt < 2; nt++) {
            int kb = wn * 16 + nt * 8 + tig * 2;
            float v0 = s[nt][0] * scale, v1 = s[nt][1] * scale;
            float v2 = s[nt][2] * scale, v3 = s[nt][3] * scale;
            if (kb + off     > r0)     v0 = -1e30f;
            if (kb + 1 + off > r0)     v1 = -1e30f;
            if (kb + off     > r0 + 8) v2 = -1e30f;
            if (kb + 1 + off > r0 + 8) v3 = -1e30f;
            Ps[r0 * APSD + kb]           = v0;
            Ps[r0 * APSD + kb + 1]       = v1;
            Ps[(r0 + 8) * APSD + kb]     = v2;
            Ps[(r0 + 8) * APSD + kb + 1] = v3;
        }
        __syncthreads();   // (c) Ps ready; K reads done -> union free

        // ---- V[kt] via cp.async ----
        {
            const float* vg = g_v + (size_t)(b * T_ + kt * 64) * C_;
#pragma unroll
            for (int e = 0; e < 8; e++) {
                int idx = tid + e * 256;
                CP_ASYNC16(sma(&KV[(idx >> 5) * AVSD + (idx & 31) * 4]),
                           vg + (size_t)idx * 4);
            }
            CP_COMMIT();
        }

        // ---- online softmax ----
        {
            int r = tid >> 3, seg = tid & 7;
            float* pr = Ps + r * APSD + seg * 8;
            float4 p0 = *(float4*)(pr), p1 = *(float4*)(pr + 4);
            float mx = fmaxf(fmaxf(fmaxf(p0.x, p0.y), fmaxf(p0.z, p0.w)),
                             fmaxf(fmaxf(p1.x, p1.y), fmaxf(p1.z, p1.w)));
            mx = fmaxf(mx, __shfl_xor_sync(0xffffffffu, mx, 1));
            mx = fmaxf(mx, __shfl_xor_sync(0xffffffffu, mx, 2));
            mx = fmaxf(mx, __shfl_xor_sync(0xffffffffu, mx, 4));
            float mold = mrow[r];
            float newm = fmaxf(mold, mx);
            float fac  = __expf(mold - newm);
            p0.x = __expf(p0.x - newm); p0.y = __expf(p0.y - newm);
            p0.z = __expf(p0.z - newm); p0.w = __expf(p0.w - newm);
            p1.x = __expf(p1.x - newm); p1.y = __expf(p1.y - newm);
            p1.z = __expf(p1.z - newm); p1.w = __expf(p1.w - newm);
            float sum = (p0.x + p0.y + p0.z + p0.w) + (p1.x + p1.y + p1.z + p1.w);
            *(float4*)(pr)     = tfr4(p0);
            *(float4*)(pr + 4) = tfr4(p1);
            sum += __shfl_xor_sync(0xffffffffu, sum, 1);
            sum += __shfl_xor_sync(0xffffffffu, sum, 2);
            sum += __shfl_xor_sync(0xffffffffu, sum, 4);
            if (seg == 0) {
                lrow[r] = lrow[r] * fac + sum;
                mrow[r] = newm;
                srow[r] = fac;
            }
        }
        CP_WAIT0();
        __syncthreads();   // (d) V + probs + stats visible

        {
            float f0 = srow[r0], f1 = srow[r0 + 8];
#pragma unroll
            for (int nt = 0; nt < 4; nt++) {
                o[nt][0] *= f0; o[nt][1] *= f0;
                o[nt][2] *= f1; o[nt][3] *= f1;
            }
        }

        // ---- phase B: O += P @ V ----
#pragma unroll 2
        for (int ks = 0; ks < 8; ks++) {
            const int c0 = ks * 8 + tig;
            uint32_t a[4];
            a[0] = U_(Ps[r0 * APSD + c0]);
            a[1] = U_(Ps[(r0 + 8) * APSD + c0]);
            a[2] = U_(Ps[r0 * APSD + c0 + 4]);
            a[3] = U_(Ps[(r0 + 8) * APSD + c0 + 4]);
#pragma unroll
            for (int nt = 0; nt < 4; nt++) {
                int n = wn * 32 + nt * 8 + gid;
                uint32_t b0 = U_(KV[(ks * 8 + tig) * AVSD + n]);
                uint32_t b1 = U_(KV[(ks * 8 + tig + 4) * AVSD + n]);
                mma8(o[nt], a, b0, b1);
            }
        }
        __syncthreads();   // (a) phase B done; union free

        // ---- K[kt+1] via cp.async ----
        if (kt + 1 < kt1) {
            const float* kg = g_k + (size_t)(b * T_ + (kt + 1) * 64) * C_;
#pragma unroll
            for (int e = 0; e < 8; e++) {
                int idx = tid + e * 256;
                CP_ASYNC16(sma(&KV[(idx >> 5) * AKSD + (idx & 31) * 4]),
                           kg + (size_t)idx * 4);
            }
            CP_COMMIT();
            CP_WAIT0();
        }
        __syncthreads();   // (b) K visible
    }

    // ---- epilogue ----
    if (!isplit) {
        float inv0 = 1.f / lrow[r0], inv1 = 1.f / lrow[r0 + 8];
        size_t base = (size_t)(b * T_ + q32 * 32);
#pragma unroll
        for (int nt = 0; nt < 4; nt++) {
            int c = wn * 32 + nt * 8 + tig * 2;
            *(float2*)(out + (base + r0) * C_ + c)     = make_float2(o[nt][0] * inv0, o[nt][1] * inv0);
            *(float2*)(out + (base + r0 + 8) * C_ + c) = make_float2(o[nt][2] * inv1, o[nt][3] * inv1);
        }
    } else {
        const size_t p = ((size_t)(b * 32 + (q32 - 32)) * 2 + sp);
        float* po = g_po + p * (32 * 128);
#pragma unroll
        for (int nt = 0; nt < 4; nt++) {
            int c = wn * 32 + nt * 8 + tig * 2;
            *(float2*)(po + (size_t)r0 * C_ + c)       = make_float2(o[nt][0], o[nt][1]);
            *(float2*)(po + (size_t)(r0 + 8) * C_ + c) = make_float2(o[nt][2], o[nt][3]);
        }
        if (tid < 32) {
            g_pm[p * 32 + tid] = mrow[tid];
            g_pl[p * 32 + tid] = lrow[tid];
        }
    }
}

// ---------------------------------------------------------------------------
// Kernel 3: merge split-K partials for heavy tiles.
// grid = 256 (b x 32 heavy q-tiles), block = 256: thread -> 16 contiguous cols.
// ---------------------------------------------------------------------------
__global__ __launch_bounds__(256) void attn_merge(float* __restrict__ out)
{
    const int p = blockIdx.x;
    const int b = p >> 5, hq = p & 31;
    const int q32 = hq + 32;
    const int tid = threadIdx.x;
    const int row = tid >> 3, cs = (tid & 7) * 16;

    const size_t p0 = ((size_t)(b * 32 + hq) * 2);
    const float* o1 = g_po + p0 * (32 * 128) + (size_t)row * 128 + cs;
    const float* o2 = o1 + 32 * 128;
    float m1 = g_pm[p0 * 32 + row], m2 = g_pm[(p0 + 1) * 32 + row];
    float l1 = g_pl[p0 * 32 + row], l2 = g_pl[(p0 + 1) * 32 + row];

    float m = fmaxf(m1, m2);
    float w1 = __expf(m1 - m), w2 = __expf(m2 - m);
    float inv = 1.f / (l1 * w1 + l2 * w2);

    float* dst = out + (size_t)(b * T_ + q32 * 32 + row) * C_ + cs;
#pragma unroll
    for (int e = 0; e < 4; e++) {
        float4 a = *(const float4*)(o1 + e * 4);
        float4 c = *(const float4*)(o2 + e * 4);
        *(float4*)(dst + e * 4) = make_float4(
            (a.x * w1 + c.x * w2) * inv, (a.y * w1 + c.y * w2) * inv,
            (a.z * w1 + c.z * w2) * inv, (a.w * w1 + c.w * w2) * inv);
    }
}

// ---------------------------------------------------------------------------
extern "C" void kernel_launch(void* const* d_in, const int* in_sizes, int n_in,
                              void* d_out, int out_size)
{
    const float* x  = (const float*)d_in[0];
    const float* Wk = (const float*)d_in[1];
    const float* Wq = (const float*)d_in[2];
    const float* Wv = (const float*)d_in[3];
    float* out = (float*)d_out;

    cudaFuncSetAttribute(qkv_mma,
                         cudaFuncAttributeMaxDynamicSharedMemorySize,
                         QKV_SMEM_BYTES);
    cudaFuncSetAttribute(attn_mma,
                         cudaFuncAttributeMaxDynamicSharedMemorySize,
                         ATTN_SMEM_BYTES);

    dim3 qkv_grid(128, 3);
    qkv_mma<<<qkv_grid, 256, QKV_SMEM_BYTES>>>(x, Wk, Wq, Wv);

    attn_mma<<<8 * 96, 256, ATTN_SMEM_BYTES>>>(out);
    attn_merge<<<256, 256>>>(out);
}